// round 1
// baseline (speedup 1.0000x reference)
#include <cuda_runtime.h>
#include <math.h>

#define BB 64
#define TT 256
#define DD 512
#define HH 1024
#define FH 4096
#define OO 512

// ---------------- scratch (device globals; no allocation) ----------------
__device__ float g_xz[(size_t)TT * BB * FH];      // 256 MB, reused for both layers
__device__ float g_h1seq[(size_t)TT * BB * HH];   // 64 MB
__device__ float g_hbuf[2][BB * HH];
__device__ float g_cbuf[2][BB * HH];

// ---------------- zero the recurrent state ----------------
__global__ void zero_state_kernel() {
    int i = blockIdx.x * blockDim.x + threadIdx.x;
    if (i < BB * HH) {
        g_hbuf[0][i] = 0.0f;
        g_cbuf[0][i] = 0.0f;
    }
}

// ---------------- generic tiled SGEMM ----------------
// C[orow(m)][n] = sum_k A[m][k]*Wt[k][n] + bias[n]
// MODE 0: orow = (m%256)*64 + m/256   (xz1: A rows are (b,t), out is [t][b][:])
// MODE 1: orow = m
// BM=BN=64, BK=16, 256 threads, 4x4 per thread, double-buffered SMEM.
template <int MODE>
__global__ __launch_bounds__(256) void gemm64_kernel(
    const float* __restrict__ A, const float* __restrict__ Wt,
    const float* __restrict__ bias, float* __restrict__ Cout,
    int K, int N)
{
    __shared__ float As[2][16 * 68];   // [k][m] transposed, padded stride 68
    __shared__ float Bs[2][16 * 64];   // [k][n]

    const int m0 = blockIdx.y * 64;
    const int n0 = blockIdx.x * 64;
    const int tid = threadIdx.x;
    const int tn = tid & 15;       // 0..15
    const int tm = tid >> 4;       // 0..15

    // A-tile load mapping: each thread loads one float4 (same m, 4 k's)
    const int am = tid >> 2;             // 0..63
    const int ak = (tid & 3) * 4;        // 0,4,8,12
    // B-tile load mapping: one float4 (same k, 4 n's)
    const int bk = tid >> 4;             // 0..15
    const int bn = (tid & 15) * 4;       // 0..60

    const float* Aptr = A + (size_t)(m0 + am) * K + ak;
    const float* Bptr = Wt + (size_t)bk * N + n0 + bn;

    float acc[4][4] = {};
    float4 areg, breg;

    const int nchunk = K / 16;

    // preload chunk 0
    areg = *(const float4*)(Aptr);
    breg = *(const float4*)(Bptr);
    {
        float* as = As[0];
        float* bs = Bs[0];
        as[(ak + 0) * 68 + am] = areg.x;
        as[(ak + 1) * 68 + am] = areg.y;
        as[(ak + 2) * 68 + am] = areg.z;
        as[(ak + 3) * 68 + am] = areg.w;
        *(float4*)&bs[bk * 64 + bn] = breg;
    }
    __syncthreads();

    for (int c = 0; c < nchunk; ++c) {
        if (c + 1 < nchunk) {
            areg = *(const float4*)(Aptr + (c + 1) * 16);
            breg = *(const float4*)(Bptr + (size_t)(c + 1) * 16 * N);
        }
        const float* as = As[c & 1];
        const float* bs = Bs[c & 1];
#pragma unroll
        for (int k = 0; k < 16; ++k) {
            float4 a4 = *(const float4*)&as[k * 68 + 4 * tm];
            float4 b4 = *(const float4*)&bs[k * 64 + 4 * tn];
            acc[0][0] += a4.x * b4.x; acc[0][1] += a4.x * b4.y;
            acc[0][2] += a4.x * b4.z; acc[0][3] += a4.x * b4.w;
            acc[1][0] += a4.y * b4.x; acc[1][1] += a4.y * b4.y;
            acc[1][2] += a4.y * b4.z; acc[1][3] += a4.y * b4.w;
            acc[2][0] += a4.z * b4.x; acc[2][1] += a4.z * b4.y;
            acc[2][2] += a4.z * b4.z; acc[2][3] += a4.z * b4.w;
            acc[3][0] += a4.w * b4.x; acc[3][1] += a4.w * b4.y;
            acc[3][2] += a4.w * b4.z; acc[3][3] += a4.w * b4.w;
        }
        if (c + 1 < nchunk) {
            float* asw = As[(c + 1) & 1];
            float* bsw = Bs[(c + 1) & 1];
            asw[(ak + 0) * 68 + am] = areg.x;
            asw[(ak + 1) * 68 + am] = areg.y;
            asw[(ak + 2) * 68 + am] = areg.z;
            asw[(ak + 3) * 68 + am] = areg.w;
            *(float4*)&bsw[bk * 64 + bn] = breg;
        }
        __syncthreads();
    }

    // epilogue: bias + store (with optional row remap)
#pragma unroll
    for (int i = 0; i < 4; ++i) {
        int m = m0 + 4 * tm + i;
        int orow = (MODE == 0) ? ((m & 255) * 64 + (m >> 8)) : m;
        float4 v;
        v.x = acc[i][0] + bias[n0 + 4 * tn + 0];
        v.y = acc[i][1] + bias[n0 + 4 * tn + 1];
        v.z = acc[i][2] + bias[n0 + 4 * tn + 2];
        v.w = acc[i][3] + bias[n0 + 4 * tn + 3];
        *(float4*)&Cout[(size_t)orow * N + n0 + 4 * tn] = v;
    }
}

// ---------------- fused LSTM step ----------------
// For one timestep t:
//   z[b][g*H+u] = xz_t[b][g*H+u] + sum_k h_in[b][k] * U[k][g*H+u]
//   c_new = sig(zf)*c + sig(zi)*tanh(zg);  h_new = sig(zo)*tanh(c_new)
// Grid: H/8 = 128 CTAs, 128 threads. Each CTA: 8 units x all 64 batches x 4 gates.
// Per-thread: 4 batches x 1 unit x 4 gates = 16 accumulators.
__global__ __launch_bounds__(128) void lstm_step_kernel(
    const float* __restrict__ xz_t,   // [B][4H]
    const float* __restrict__ U,      // [H][4H]
    const float* __restrict__ h_in,   // [B][H]
    const float* __restrict__ c_in,   // [B][H]
    float* __restrict__ h_out,
    float* __restrict__ c_out,
    float* __restrict__ hseq_out)     // [B][H] slot or nullptr
{
    __shared__ float hs[2][16 * 64];        // [k][b]
    __shared__ float us[2][4 * 16 * 8];     // [g][k][u]

    const int tid = threadIdx.x;
    const int u0 = blockIdx.x * 8;
    const int txu = tid & 7;        // unit within tile
    const int txb = tid >> 3;       // 0..15 -> batches 4*txb..+3

    // h tile loaders: thread -> (b = tid&63, k-half = tid>>6), 8 floats each
    const int lb = tid & 63;
    const int lkh = tid >> 6;       // 0 or 1
    // U tile loaders: one float4 each
    const int lj = (tid & 1) * 4;
    const int lk = (tid >> 1) & 15;
    const int lg = tid >> 5;        // 0..3

    const float* hptr = h_in + (size_t)lb * HH + lkh * 8;
    const float* uptr = U + (size_t)lk * FH + lg * HH + u0 + lj;

    float acc[4][4] = {};  // [gate][batch_i]
    float4 hr0, hr1, ur;

    const int NCH = HH / 16;  // 64

    // preload chunk 0
    hr0 = *(const float4*)(hptr);
    hr1 = *(const float4*)(hptr + 4);
    ur  = *(const float4*)(uptr);
    {
        float* hw = hs[0];
        float* uw = us[0];
        const int kb = lkh * 8;
        hw[(kb + 0) * 64 + lb] = hr0.x;
        hw[(kb + 1) * 64 + lb] = hr0.y;
        hw[(kb + 2) * 64 + lb] = hr0.z;
        hw[(kb + 3) * 64 + lb] = hr0.w;
        hw[(kb + 4) * 64 + lb] = hr1.x;
        hw[(kb + 5) * 64 + lb] = hr1.y;
        hw[(kb + 6) * 64 + lb] = hr1.z;
        hw[(kb + 7) * 64 + lb] = hr1.w;
        *(float4*)&uw[(lg * 16 + lk) * 8 + lj] = ur;
    }
    __syncthreads();

    for (int c = 0; c < NCH; ++c) {
        if (c + 1 < NCH) {
            hr0 = *(const float4*)(hptr + (c + 1) * 16);
            hr1 = *(const float4*)(hptr + (c + 1) * 16 + 4);
            ur  = *(const float4*)(uptr + (size_t)(c + 1) * 16 * FH);
        }
        const float* h_ = hs[c & 1];
        const float* u_ = us[c & 1];
#pragma unroll
        for (int k = 0; k < 16; ++k) {
            float4 hv = *(const float4*)&h_[k * 64 + 4 * txb];
            float ug0 = u_[(0 * 16 + k) * 8 + txu];
            float ug1 = u_[(1 * 16 + k) * 8 + txu];
            float ug2 = u_[(2 * 16 + k) * 8 + txu];
            float ug3 = u_[(3 * 16 + k) * 8 + txu];
            acc[0][0] += hv.x * ug0; acc[0][1] += hv.y * ug0;
            acc[0][2] += hv.z * ug0; acc[0][3] += hv.w * ug0;
            acc[1][0] += hv.x * ug1; acc[1][1] += hv.y * ug1;
            acc[1][2] += hv.z * ug1; acc[1][3] += hv.w * ug1;
            acc[2][0] += hv.x * ug2; acc[2][1] += hv.y * ug2;
            acc[2][2] += hv.z * ug2; acc[2][3] += hv.w * ug2;
            acc[3][0] += hv.x * ug3; acc[3][1] += hv.y * ug3;
            acc[3][2] += hv.z * ug3; acc[3][3] += hv.w * ug3;
        }
        if (c + 1 < NCH) {
            float* hw = hs[(c + 1) & 1];
            float* uw = us[(c + 1) & 1];
            const int kb = lkh * 8;
            hw[(kb + 0) * 64 + lb] = hr0.x;
            hw[(kb + 1) * 64 + lb] = hr0.y;
            hw[(kb + 2) * 64 + lb] = hr0.z;
            hw[(kb + 3) * 64 + lb] = hr0.w;
            hw[(kb + 4) * 64 + lb] = hr1.x;
            hw[(kb + 5) * 64 + lb] = hr1.y;
            hw[(kb + 6) * 64 + lb] = hr1.z;
            hw[(kb + 7) * 64 + lb] = hr1.w;
            *(float4*)&uw[(lg * 16 + lk) * 8 + lj] = ur;
        }
        __syncthreads();
    }

    // epilogue: gates
    const int u = u0 + txu;
#pragma unroll
    for (int i = 0; i < 4; ++i) {
        int b = 4 * txb + i;
        float zi = acc[0][i] + xz_t[(size_t)b * FH + 0 * HH + u];
        float zf = acc[1][i] + xz_t[(size_t)b * FH + 1 * HH + u];
        float zg = acc[2][i] + xz_t[(size_t)b * FH + 2 * HH + u];
        float zo = acc[3][i] + xz_t[(size_t)b * FH + 3 * HH + u];
        float si = 1.0f / (1.0f + expf(-zi));
        float sf = 1.0f / (1.0f + expf(-zf));
        float so = 1.0f / (1.0f + expf(-zo));
        float cn = sf * c_in[(size_t)b * HH + u] + si * tanhf(zg);
        float hn = so * tanhf(cn);
        c_out[(size_t)b * HH + u] = cn;
        h_out[(size_t)b * HH + u] = hn;
        if (hseq_out) hseq_out[(size_t)b * HH + u] = hn;
    }
}

// ---------------- launch ----------------
extern "C" void kernel_launch(void* const* d_in, const int* in_sizes, int n_in,
                              void* d_out, int out_size)
{
    const float* x  = (const float*)d_in[0];
    const float* W1 = (const float*)d_in[1];
    const float* U1 = (const float*)d_in[2];
    const float* b1 = (const float*)d_in[3];
    const float* W2 = (const float*)d_in[4];
    const float* U2 = (const float*)d_in[5];
    const float* b2 = (const float*)d_in[6];
    const float* Wd = (const float*)d_in[7];
    const float* bd = (const float*)d_in[8];
    float* out = (float*)d_out;

    float *xz, *h1seq, *hbuf, *cbuf;
    cudaGetSymbolAddress((void**)&xz, g_xz);
    cudaGetSymbolAddress((void**)&h1seq, g_h1seq);
    cudaGetSymbolAddress((void**)&hbuf, g_hbuf);
    cudaGetSymbolAddress((void**)&cbuf, g_cbuf);

    const dim3 gxz(FH / 64, (BB * TT) / 64);   // (64, 256)

    // ---- layer 1: xz1 = x @ W1 + b1, laid out as [t][b][4H] ----
    gemm64_kernel<0><<<gxz, 256>>>(x, W1, b1, xz, DD, FH);

    zero_state_kernel<<<(BB * HH + 255) / 256, 256>>>();
    for (int t = 0; t < TT; ++t) {
        int in  = t & 1;
        int outb = in ^ 1;
        lstm_step_kernel<<<HH / 8, 128>>>(
            xz + (size_t)t * BB * FH, U1,
            hbuf + (size_t)in * BB * HH,  cbuf + (size_t)in * BB * HH,
            hbuf + (size_t)outb * BB * HH, cbuf + (size_t)outb * BB * HH,
            h1seq + (size_t)t * BB * HH);
    }

    // ---- layer 2: xz2 = h1seq @ W2 + b2 (rows already [t][b]) ----
    gemm64_kernel<1><<<gxz, 256>>>(h1seq, W2, b2, xz, HH, FH);

    zero_state_kernel<<<(BB * HH + 255) / 256, 256>>>();
    for (int t = 0; t < TT; ++t) {
        int in  = t & 1;
        int outb = in ^ 1;
        lstm_step_kernel<<<HH / 8, 128>>>(
            xz + (size_t)t * BB * FH, U2,
            hbuf + (size_t)in * BB * HH,  cbuf + (size_t)in * BB * HH,
            hbuf + (size_t)outb * BB * HH, cbuf + (size_t)outb * BB * HH,
            nullptr);
    }

    // ---- final dense: out = h_last @ Wd + bd; h_last is hbuf[0] (t=255 wrote buf 0) ----
    const dim3 gd(OO / 64, BB / 64);   // (8, 1)
    gemm64_kernel<1><<<gd, 256>>>(hbuf, Wd, bd, out, HH, OO);
}

// round 7
// speedup vs baseline: 3.3315x; 3.3315x over previous
#include <cuda_runtime.h>
#include <cuda_bf16.h>
#include <math.h>
#include <stdint.h>

typedef __nv_bfloat16 bf16;

#define BB 64
#define TT 256
#define DD 512
#define HH 1024
#define FH 4096
#define OO 512
#define MROWS (BB*TT)

// ---------------- scratch (device globals; no allocation) ----------------
__device__ float g_xz[(size_t)MROWS * FH];
__device__ bf16  g_xhi[(size_t)MROWS * DD];
__device__ bf16  g_xlo[(size_t)MROWS * DD];
__device__ bf16  g_w1t_hi[(size_t)FH * DD];
__device__ bf16  g_w1t_lo[(size_t)FH * DD];
__device__ bf16  g_u1t_hi[(size_t)FH * HH];
__device__ bf16  g_u1t_lo[(size_t)FH * HH];
__device__ bf16  g_w2t_hi[(size_t)FH * HH];
__device__ bf16  g_w2t_lo[(size_t)FH * HH];
__device__ bf16  g_u2t_hi[(size_t)FH * HH];
__device__ bf16  g_u2t_lo[(size_t)FH * HH];
__device__ bf16  g_h1hi[(size_t)MROWS * HH];
__device__ bf16  g_h1lo[(size_t)MROWS * HH];
__device__ bf16  g_hshi[2][BB * HH];
__device__ bf16  g_hslo[2][BB * HH];
__device__ float g_c[BB * HH];
__device__ float g_hfp[BB * HH];
__device__ float g_b1p[FH];
__device__ float g_b2p[FH];
__device__ int   g_barcnt;
__device__ int   g_barsense;

// ---------------- ptx helpers (arch-generic, no tcgen05) ----------------
__device__ __forceinline__ uint32_t smem_u32(const void* p) {
    return (uint32_t)__cvta_generic_to_shared(p);
}
__device__ __forceinline__ void ldsm_x4(uint32_t& r0, uint32_t& r1, uint32_t& r2,
                                        uint32_t& r3, uint32_t a) {
    asm volatile("ldmatrix.sync.aligned.m8n8.x4.shared.b16 {%0,%1,%2,%3}, [%4];"
                 : "=r"(r0), "=r"(r1), "=r"(r2), "=r"(r3) : "r"(a));
}
__device__ __forceinline__ void mma16816(float* d, uint32_t a0, uint32_t a1,
                                         uint32_t a2, uint32_t a3,
                                         uint32_t b0, uint32_t b1) {
    asm volatile(
        "mma.sync.aligned.m16n8k16.row.col.f32.bf16.bf16.f32 "
        "{%0,%1,%2,%3}, {%4,%5,%6,%7}, {%8,%9}, {%0,%1,%2,%3};"
        : "+f"(d[0]), "+f"(d[1]), "+f"(d[2]), "+f"(d[3])
        : "r"(a0), "r"(a1), "r"(a2), "r"(a3), "r"(b0), "r"(b1));
}
__device__ __forceinline__ void cpasync16(uint32_t s, const void* g) {
    asm volatile("cp.async.cg.shared.global [%0], [%1], 16;" :: "r"(s), "l"(g));
}
#define CP_COMMIT() asm volatile("cp.async.commit_group;" ::: "memory")
#define CP_WAIT1()  asm volatile("cp.async.wait_group 1;" ::: "memory")
#define CP_WAIT0()  asm volatile("cp.async.wait_group 0;" ::: "memory")

// swizzled offset within a tile of 128B rows: row*128 + ((col16 ^ (row&7))*16)
__device__ __forceinline__ uint32_t swz(int row, int col16) {
    return (uint32_t)(row * 128 + ((col16 ^ (row & 7)) * 16));
}

// cp.async a [R rows x 64 bf16] chunk (kc-th) from K-major gmem into swizzled smem
template <int R, int NT>
__device__ __forceinline__ void cp_tile(const bf16* __restrict__ src, size_t row0,
                                        int K, int kc, uint32_t sdst, int tid) {
#pragma unroll
    for (int i = tid; i < R * 8; i += NT) {
        int r = i >> 3, j = i & 7;
        cpasync16(sdst + swz(r, j), src + (row0 + r) * (size_t)K + (size_t)kc * 64 + j * 8);
    }
}

// ---------------- preprocessing ----------------
__global__ void split_x_kernel(const float* __restrict__ x, bf16* __restrict__ hi,
                               bf16* __restrict__ lo, int n) {
    int i = blockIdx.x * blockDim.x + threadIdx.x;
    if (i < n) {
        float v = x[i];
        bf16 h = __float2bfloat16(v);
        hi[i] = h;
        lo[i] = __float2bfloat16(v - __bfloat162float(h));
    }
}

// W [K][4096] -> out [4096][K] K-major with gate permute n' = 4u+g (src n = g*1024+u)
__global__ void split_wT_kernel(const float* __restrict__ W, bf16* __restrict__ hiT,
                                bf16* __restrict__ loT, int K) {
    __shared__ float t[32][33];
    int kb = blockIdx.y * 32, nb = blockIdx.x * 32;
    for (int r = threadIdx.y; r < 32; r += 8)
        t[r][threadIdx.x] = W[(size_t)(kb + r) * FH + nb + threadIdx.x];
    __syncthreads();
    for (int c = threadIdx.y; c < 32; c += 8) {
        int n = nb + c;
        int np = ((n & 1023) << 2) | (n >> 10);
        float v = t[threadIdx.x][c];
        bf16 h = __float2bfloat16(v);
        hiT[(size_t)np * K + kb + threadIdx.x] = h;
        loT[(size_t)np * K + kb + threadIdx.x] = __float2bfloat16(v - __bfloat162float(h));
    }
}

__global__ void permute_bias_kernel(const float* __restrict__ b, float* __restrict__ bp) {
    int np = blockIdx.x * blockDim.x + threadIdx.x;
    if (np < FH) { int u = np >> 2, g = np & 3; bp[np] = b[g * HH + u]; }
}

__global__ void zero_state_kernel() {
    int i = blockIdx.x * blockDim.x + threadIdx.x;
    if (i < BB * HH) g_c[i] = 0.0f;
    if (i < (BB * HH) / 2) {
        ((uint32_t*)g_hshi[0])[i] = 0u;
        ((uint32_t*)g_hslo[0])[i] = 0u;
    }
    if (i == 0) { g_barcnt = 0; g_barsense = 0; }
}

// ---------------- big split-bf16 GEMM: out[M][4096] = A @ B^T + bias ----------------
// Tile 128x128, BK=64, 256 thr (8 warps: 2M x 4N), warp tile 64x32.
// REMAP=1: orow = (m&255)*64 + (m>>8)   (layer-1: rows (b,t) -> [t][b])
template <int REMAP>
__global__ __launch_bounds__(256) void hgemm_kernel(
    const bf16* __restrict__ Ahi, const bf16* __restrict__ Alo,
    const bf16* __restrict__ Bhi, const bf16* __restrict__ Blo,
    const float* __restrict__ bias, float* __restrict__ out, int K)
{
    extern __shared__ char smem[];
    const int tid = threadIdx.x;
    const int wid = tid >> 5, lane = tid & 31;
    const int wm = wid >> 2, wn = wid & 3;
    const int m0 = blockIdx.y * 128, n0 = blockIdx.x * 128;
    uint32_t sb = smem_u32(smem);
    const int nkc = K >> 6;

    // stage s at s*65536: Ahi@0 Alo@16384 Bhi@32768 Blo@49152
    {
        uint32_t st = sb;
        cp_tile<128, 256>(Ahi, m0, K, 0, st, tid);
        cp_tile<128, 256>(Alo, m0, K, 0, st + 16384, tid);
        cp_tile<128, 256>(Bhi, n0, K, 0, st + 32768, tid);
        cp_tile<128, 256>(Blo, n0, K, 0, st + 49152, tid);
        CP_COMMIT();
    }

    float acc[4][4][4] = {};   // [mt][nb][reg]

    // ldmatrix lane address components
    const int a_row = wm * 64 + (lane & 7) + ((lane >> 3) & 1) * 8;  // + mt*16
    const int a_cp  = (lane >> 4) & 1;                               // + kj*2
    const int b_row = wn * 32 + (lane & 7) + ((lane >> 4) & 1) * 8;  // + nbp*16
    const int b_cp  = (lane >> 3) & 1;                               // + kj*2

    for (int kc = 0; kc < nkc; ++kc) {
        int cur = kc & 1;
        if (kc + 1 < nkc) {
            uint32_t st = sb + (uint32_t)(cur ^ 1) * 65536u;
            cp_tile<128, 256>(Ahi, m0, K, kc + 1, st, tid);
            cp_tile<128, 256>(Alo, m0, K, kc + 1, st + 16384, tid);
            cp_tile<128, 256>(Bhi, n0, K, kc + 1, st + 32768, tid);
            cp_tile<128, 256>(Blo, n0, K, kc + 1, st + 49152, tid);
            CP_COMMIT();
            CP_WAIT1();
        } else {
            CP_WAIT0();
        }
        __syncthreads();
        uint32_t stA = sb + (uint32_t)cur * 65536u;
        uint32_t stB = stA + 32768;
#pragma unroll
        for (int kj = 0; kj < 4; ++kj) {
            // B frags: 2 x4 per hi/lo (each covers 2 n8 blocks)
            uint32_t bh[4][2], bl[4][2];
#pragma unroll
            for (int nbp = 0; nbp < 2; ++nbp) {
                uint32_t baddr = stB + swz(b_row + nbp * 16, kj * 2 + b_cp);
                ldsm_x4(bh[nbp * 2][0], bh[nbp * 2][1], bh[nbp * 2 + 1][0], bh[nbp * 2 + 1][1], baddr);
                ldsm_x4(bl[nbp * 2][0], bl[nbp * 2][1], bl[nbp * 2 + 1][0], bl[nbp * 2 + 1][1], baddr + 16384);
            }
#pragma unroll
            for (int mt = 0; mt < 4; ++mt) {
                uint32_t aaddr = stA + swz(a_row + mt * 16, kj * 2 + a_cp);
                uint32_t ah0, ah1, ah2, ah3, al0, al1, al2, al3;
                ldsm_x4(ah0, ah1, ah2, ah3, aaddr);
                ldsm_x4(al0, al1, al2, al3, aaddr + 16384);
#pragma unroll
                for (int nb = 0; nb < 4; ++nb) {
                    mma16816(acc[mt][nb], ah0, ah1, ah2, ah3, bh[nb][0], bh[nb][1]);
                    mma16816(acc[mt][nb], al0, al1, al2, al3, bh[nb][0], bh[nb][1]);
                    mma16816(acc[mt][nb], ah0, ah1, ah2, ah3, bl[nb][0], bl[nb][1]);
                }
            }
        }
        __syncthreads();
    }

    // epilogue: bias + store (f32x2 per (mt, nb, half))
#pragma unroll
    for (int mt = 0; mt < 4; ++mt) {
#pragma unroll
        for (int half = 0; half < 2; ++half) {
            int m = m0 + wm * 64 + mt * 16 + (lane >> 2) + half * 8;
            size_t orow = REMAP ? ((size_t)(m & 255) * 64 + (size_t)(m >> 8)) : (size_t)m;
#pragma unroll
            for (int nb = 0; nb < 4; ++nb) {
                int n = n0 + wn * 32 + nb * 8 + 2 * (lane & 3);
                float2 v;
                v.x = acc[mt][nb][half * 2 + 0] + bias[n];
                v.y = acc[mt][nb][half * 2 + 1] + bias[n + 1];
                *(float2*)(out + orow * FH + n) = v;
            }
        }
    }
}

// ---------------- persistent LSTM layer (one launch per layer) ----------------
// 128 CTAs x 128 thr. CTA owns n' cols [32*cta, 32*cta+32) = units [8*cta, 8*cta+8).
// U tile (32 x 1024, hi+lo = 128KB) resident in SMEM all 256 steps.
// Per step: z = h @ U^T (split 3-MMA, M=64 N=32 K=1024), fused gates, grid barrier.
template <int LAYER>
__global__ __launch_bounds__(128) void lstm_persist(
    const float* __restrict__ xz,
    const bf16* __restrict__ Uhi, const bf16* __restrict__ Ulo,
    bf16* __restrict__ h0hi, bf16* __restrict__ h0lo,
    bf16* __restrict__ h1hi, bf16* __restrict__ h1lo,
    float* __restrict__ cst,
    bf16* __restrict__ seqhi, bf16* __restrict__ seqlo,
    float* __restrict__ hfp,
    int* __restrict__ barcnt, volatile int* __restrict__ barsense)
{
    extern __shared__ char smem[];
    const int tid = threadIdx.x;
    const int wid = tid >> 5, lane = tid & 31;
    const int n0 = blockIdx.x * 32;
    const int u0 = blockIdx.x * 8;
    uint32_t sb = smem_u32(smem);
    // layout: Uhi [16 kblk x 4KB] @0, Ulo @65536, h stages @131072 + s*16384 {hi,lo 8KB},
    //         z @163840 (64 x 36 f32)
    float* zs = (float*)(smem + 163840);

    // load U tile once (plain ldg + swizzled sts)
    for (int i = tid; i < 16 * 32 * 8; i += 128) {
        int kb = i >> 8;
        int r = (i >> 3) & 31;
        int j = i & 7;
        size_t goff = (size_t)(n0 + r) * HH + kb * 64 + j * 8;
        uint32_t off = (uint32_t)(kb * 4096) + swz(r, j);
        *(uint4*)(smem + off)         = *(const uint4*)(Uhi + goff);
        *(uint4*)(smem + 65536 + off) = *(const uint4*)(Ulo + goff);
    }

    int sense = 0;
    const int a_row = wid * 16 + (lane & 7) + ((lane >> 3) & 1) * 8;
    const int a_cp  = (lane >> 4) & 1;
    const int b_row = (lane & 7) + ((lane >> 4) & 1) * 8;   // + nbp*16
    const int b_cp  = (lane >> 3) & 1;
    __syncthreads();

    for (int t = 0; t < TT; ++t) {
        const bf16* hhi = (t & 1) ? h1hi : h0hi;
        const bf16* hlo = (t & 1) ? h1lo : h0lo;
        bf16* ohhi = (t & 1) ? h0hi : h1hi;
        bf16* ohlo = (t & 1) ? h0lo : h1lo;
        const float* xzt = xz + (size_t)t * BB * FH;

        float acc[4][4] = {};   // [nb][reg]

        {   // prime stage 0 with chunk 0 of h
            uint32_t s0 = sb + 131072;
#pragma unroll
            for (int i = tid; i < 64 * 8; i += 128) {
                int r = i >> 3, j = i & 7;
                uint32_t off = swz(r, j);
                cpasync16(s0 + off,        hhi + (size_t)r * HH + j * 8);
                cpasync16(s0 + 8192 + off, hlo + (size_t)r * HH + j * 8);
            }
            CP_COMMIT();
        }
        for (int kc = 0; kc < 16; ++kc) {
            int cur = kc & 1;
            if (kc + 1 < 16) {
                uint32_t sn = sb + 131072 + (uint32_t)(cur ^ 1) * 16384u;
#pragma unroll
                for (int i = tid; i < 64 * 8; i += 128) {
                    int r = i >> 3, j = i & 7;
                    uint32_t off = swz(r, j);
                    cpasync16(sn + off,        hhi + (size_t)r * HH + (kc + 1) * 64 + j * 8);
                    cpasync16(sn + 8192 + off, hlo + (size_t)r * HH + (kc + 1) * 64 + j * 8);
                }
                CP_COMMIT();
                CP_WAIT1();
            } else {
                CP_WAIT0();
            }
            __syncthreads();
            uint32_t hA = sb + 131072 + (uint32_t)cur * 16384u;
            uint32_t uB = sb + (uint32_t)kc * 4096u;
#pragma unroll
            for (int kj = 0; kj < 4; ++kj) {
                uint32_t aaddr = hA + swz(a_row, kj * 2 + a_cp);
                uint32_t ah0, ah1, ah2, ah3, al0, al1, al2, al3;
                ldsm_x4(ah0, ah1, ah2, ah3, aaddr);
                ldsm_x4(al0, al1, al2, al3, aaddr + 8192);
                uint32_t bh[4][2], bl[4][2];
#pragma unroll
                for (int nbp = 0; nbp < 2; ++nbp) {
                    uint32_t baddr = uB + swz(b_row + nbp * 16, kj * 2 + b_cp);
                    ldsm_x4(bh[nbp * 2][0], bh[nbp * 2][1], bh[nbp * 2 + 1][0], bh[nbp * 2 + 1][1], baddr);
                    ldsm_x4(bl[nbp * 2][0], bl[nbp * 2][1], bl[nbp * 2 + 1][0], bl[nbp * 2 + 1][1], baddr + 65536);
                }
#pragma unroll
                for (int nb = 0; nb < 4; ++nb) {
                    mma16816(acc[nb], ah0, ah1, ah2, ah3, bh[nb][0], bh[nb][1]);
                    mma16816(acc[nb], al0, al1, al2, al3, bh[nb][0], bh[nb][1]);
                    mma16816(acc[nb], ah0, ah1, ah2, ah3, bl[nb][0], bl[nb][1]);
                }
            }
            __syncthreads();
        }
        // write z tile to smem (padded stride 36)
        {
            int m = wid * 16 + (lane >> 2);
            int n = 2 * (lane & 3);
#pragma unroll
            for (int nb = 0; nb < 4; ++nb) {
                int nn = nb * 8 + n;
                zs[m * 36 + nn]           = acc[nb][0];
                zs[m * 36 + nn + 1]       = acc[nb][1];
                zs[(m + 8) * 36 + nn]     = acc[nb][2];
                zs[(m + 8) * 36 + nn + 1] = acc[nb][3];
            }
        }
        __syncthreads();
        // epilogue: thread -> (b = tid/2, 4 units)
        {
            int b = tid >> 1;
            int uu0 = (tid & 1) * 4;
            const float* xzb = xzt + (size_t)b * FH + n0 + uu0 * 4;
            const float* zrow = zs + b * 36 + uu0 * 4;
#pragma unroll
            for (int q = 0; q < 4; ++q) {
                int ug = u0 + uu0 + q;
                float4 xv = *(const float4*)(xzb + q * 4);
                float zi = zrow[q * 4 + 0] + xv.x;
                float zf = zrow[q * 4 + 1] + xv.y;
                float zg = zrow[q * 4 + 2] + xv.z;
                float zo = zrow[q * 4 + 3] + xv.w;
                float si = 1.0f / (1.0f + __expf(-zi));
                float sf = 1.0f / (1.0f + __expf(-zf));
                float so = 1.0f / (1.0f + __expf(-zo));
                float tg = 1.0f - 2.0f / (__expf(2.0f * zg) + 1.0f);
                float cn = sf * cst[b * HH + ug] + si * tg;
                float tc = 1.0f - 2.0f / (__expf(2.0f * cn) + 1.0f);
                float hn = so * tc;
                cst[b * HH + ug] = cn;
                bf16 hh = __float2bfloat16(hn);
                bf16 hl = __float2bfloat16(hn - __bfloat162float(hh));
                ohhi[(size_t)b * HH + ug] = hh;
                ohlo[(size_t)b * HH + ug] = hl;
                if (LAYER == 1) {
                    seqhi[(size_t)t * (BB * HH) + b * HH + ug] = hh;
                    seqlo[(size_t)t * (BB * HH) + b * HH + ug] = hl;
                } else if (t == TT - 1) {
                    hfp[b * HH + ug] = hn;
                }
            }
        }
        // grid barrier (sense-reversal; all 128 CTAs resident)
        __syncthreads();
        if (tid == 0) {
            int s = sense ^ 1;
            __threadfence();
            if (atomicAdd(barcnt, 1) == 127) {
                *barcnt = 0;
                __threadfence();
                *barsense = s;
            } else {
                while (*barsense != s) { __nanosleep(40); }
            }
            __threadfence();
        }
        sense ^= 1;
        __syncthreads();
    }
}

// ---------------- fp32 GEMM for the tiny final dense ----------------
__global__ __launch_bounds__(256) void gemm64_kernel(
    const float* __restrict__ A, const float* __restrict__ Wt,
    const float* __restrict__ bias, float* __restrict__ Cout,
    int K, int N)
{
    __shared__ float As[2][16 * 68];
    __shared__ float Bs[2][16 * 64];
    const int m0 = blockIdx.y * 64;
    const int n0 = blockIdx.x * 64;
    const int tid = threadIdx.x;
    const int tn = tid & 15;
    const int tm = tid >> 4;
    const int am = tid >> 2;
    const int ak = (tid & 3) * 4;
    const int bk = tid >> 4;
    const int bn = (tid & 15) * 4;
    const float* Aptr = A + (size_t)(m0 + am) * K + ak;
    const float* Bptr = Wt + (size_t)bk * N + n0 + bn;
    float acc[4][4] = {};
    float4 areg, breg;
    const int nchunk = K / 16;
    areg = *(const float4*)(Aptr);
    breg = *(const float4*)(Bptr);
    {
        float* as = As[0]; float* bs = Bs[0];
        as[(ak + 0) * 68 + am] = areg.x; as[(ak + 1) * 68 + am] = areg.y;
        as[(ak + 2) * 68 + am] = areg.z; as[(ak + 3) * 68 + am] = areg.w;
        *(float4*)&bs[bk * 64 + bn] = breg;
    }
    __syncthreads();
    for (int c = 0; c < nchunk; ++c) {
        if (c + 1 < nchunk) {
            areg = *(const float4*)(Aptr + (c + 1) * 16);
            breg = *(const float4*)(Bptr + (size_t)(c + 1) * 16 * N);
        }
        const float* as = As[c & 1];
        const float* bs = Bs[c & 1];
#pragma unroll
        for (int k = 0; k < 16; ++k) {
            float4 a4 = *(const float4*)&as[k * 68 + 4 * tm];
            float4 b4 = *(const float4*)&bs[k * 64 + 4 * tn];
            acc[0][0] += a4.x * b4.x; acc[0][1] += a4.x * b4.y;
            acc[0][2] += a4.x * b4.z; acc[0][3] += a4.x * b4.w;
            acc[1][0] += a4.y * b4.x; acc[1][1] += a4.y * b4.y;
            acc[1][2] += a4.y * b4.z; acc[1][3] += a4.y * b4.w;
            acc[2][0] += a4.z * b4.x; acc[2][1] += a4.z * b4.y;
            acc[2][2] += a4.z * b4.z; acc[2][3] += a4.z * b4.w;
            acc[3][0] += a4.w * b4.x; acc[3][1] += a4.w * b4.y;
            acc[3][2] += a4.w * b4.z; acc[3][3] += a4.w * b4.w;
        }
        if (c + 1 < nchunk) {
            float* asw = As[(c + 1) & 1]; float* bsw = Bs[(c + 1) & 1];
            asw[(ak + 0) * 68 + am] = areg.x; asw[(ak + 1) * 68 + am] = areg.y;
            asw[(ak + 2) * 68 + am] = areg.z; asw[(ak + 3) * 68 + am] = areg.w;
            *(float4*)&bsw[bk * 64 + bn] = breg;
        }
        __syncthreads();
    }
#pragma unroll
    for (int i = 0; i < 4; ++i) {
        int m = m0 + 4 * tm + i;
        float4 v;
        v.x = acc[i][0] + bias[n0 + 4 * tn + 0];
        v.y = acc[i][1] + bias[n0 + 4 * tn + 1];
        v.z = acc[i][2] + bias[n0 + 4 * tn + 2];
        v.w = acc[i][3] + bias[n0 + 4 * tn + 3];
        *(float4*)&Cout[(size_t)m * N + n0 + 4 * tn] = v;
    }
}

// ---------------- launch ----------------
extern "C" void kernel_launch(void* const* d_in, const int* in_sizes, int n_in,
                              void* d_out, int out_size)
{
    const float* x  = (const float*)d_in[0];
    const float* W1 = (const float*)d_in[1];
    const float* U1 = (const float*)d_in[2];
    const float* b1 = (const float*)d_in[3];
    const float* W2 = (const float*)d_in[4];
    const float* U2 = (const float*)d_in[5];
    const float* b2 = (const float*)d_in[6];
    const float* Wd = (const float*)d_in[7];
    const float* bd = (const float*)d_in[8];
    float* out = (float*)d_out;

#define SYM(v, s) do { void* p_; cudaGetSymbolAddress(&p_, s); v = (decltype(v))p_; } while (0)
    float *xz, *b1p, *b2p, *cbuf, *hfp;
    bf16 *xhi, *xlo, *w1h, *w1l, *u1h, *u1l, *w2h, *w2l, *u2h, *u2l;
    bf16 *h1h, *h1l, *hshi, *hslo;
    int* barc; int* bars;
    SYM(xz, g_xz); SYM(b1p, g_b1p); SYM(b2p, g_b2p); SYM(cbuf, g_c); SYM(hfp, g_hfp);
    SYM(xhi, g_xhi); SYM(xlo, g_xlo);
    SYM(w1h, g_w1t_hi); SYM(w1l, g_w1t_lo); SYM(u1h, g_u1t_hi); SYM(u1l, g_u1t_lo);
    SYM(w2h, g_w2t_hi); SYM(w2l, g_w2t_lo); SYM(u2h, g_u2t_hi); SYM(u2l, g_u2t_lo);
    SYM(h1h, g_h1hi); SYM(h1l, g_h1lo); SYM(hshi, g_hshi); SYM(hslo, g_hslo);
    SYM(barc, g_barcnt); SYM(bars, g_barsense);
#undef SYM

    const int GEMM_SMEM = 2 * 65536;                    // 131072
    const int PERS_SMEM = 163840 + 64 * 36 * 4;         // 173056
    cudaFuncSetAttribute(hgemm_kernel<0>, cudaFuncAttributeMaxDynamicSharedMemorySize, GEMM_SMEM);
    cudaFuncSetAttribute(hgemm_kernel<1>, cudaFuncAttributeMaxDynamicSharedMemorySize, GEMM_SMEM);
    cudaFuncSetAttribute(lstm_persist<1>, cudaFuncAttributeMaxDynamicSharedMemorySize, PERS_SMEM);
    cudaFuncSetAttribute(lstm_persist<2>, cudaFuncAttributeMaxDynamicSharedMemorySize, PERS_SMEM);

    // preprocessing
    split_x_kernel<<<(MROWS * DD + 255) / 256, 256>>>(x, xhi, xlo, MROWS * DD);
    split_wT_kernel<<<dim3(FH / 32, DD / 32), dim3(32, 8)>>>(W1, w1h, w1l, DD);
    split_wT_kernel<<<dim3(FH / 32, HH / 32), dim3(32, 8)>>>(U1, u1h, u1l, HH);
    split_wT_kernel<<<dim3(FH / 32, HH / 32), dim3(32, 8)>>>(W2, w2h, w2l, HH);
    split_wT_kernel<<<dim3(FH / 32, HH / 32), dim3(32, 8)>>>(U2, u2h, u2l, HH);
    permute_bias_kernel<<<FH / 256, 256>>>(b1, b1p);
    permute_bias_kernel<<<FH / 256, 256>>>(b2, b2p);

    const dim3 ggrid(FH / 128, MROWS / 128);   // (32, 128)

    // layer 1: xz = x @ W1p + b1p  (rows remapped to [t][b])
    hgemm_kernel<1><<<ggrid, 256, GEMM_SMEM>>>(xhi, xlo, w1h, w1l, b1p, xz, DD);
    zero_state_kernel<<<(BB * HH + 255) / 256, 256>>>();
    lstm_persist<1><<<128, 128, PERS_SMEM>>>(
        xz, u1h, u1l,
        hshi, hslo, hshi + BB * HH, hslo + BB * HH,
        cbuf, h1h, h1l, (float*)0, barc, bars);

    // layer 2: xz = h1seq @ W2p + b2p  (rows already [t][b])
    hgemm_kernel<0><<<ggrid, 256, GEMM_SMEM>>>(h1h, h1l, w2h, w2l, b2p, xz, HH);
    zero_state_kernel<<<(BB * HH + 255) / 256, 256>>>();
    lstm_persist<2><<<128, 128, PERS_SMEM>>>(
        xz, u2h, u2l,
        hshi, hslo, hshi + BB * HH, hslo + BB * HH,
        cbuf, (bf16*)0, (bf16*)0, hfp, barc, bars);

    // final dense: out = h_last @ Wd + bd
    gemm64_kernel<<<dim3(OO / 64, BB / 64), 256>>>(hfp, Wd, bd, out, HH, OO);
}

// round 11
// speedup vs baseline: 5.0652x; 1.5204x over previous
#include <cuda_runtime.h>
#include <cuda_fp16.h>
#include <math.h>
#include <stdint.h>

typedef __half f16;

#define BB 64
#define TT 256
#define DD 512
#define HH 1024
#define FH 4096
#define OO 512
#define MROWS (BB*TT)

// ---------------- scratch (device globals; no allocation) ----------------
__device__ float g_xz[(size_t)MROWS * FH];
__device__ f16   g_x16[(size_t)MROWS * DD];
__device__ f16   g_w1t_hi[(size_t)FH * DD];
__device__ f16   g_w1t_lo[(size_t)FH * DD];
__device__ f16   g_u1t_hi[(size_t)FH * HH];
__device__ f16   g_u1t_lo[(size_t)FH * HH];
__device__ f16   g_w2t_hi[(size_t)FH * HH];
__device__ f16   g_w2t_lo[(size_t)FH * HH];
__device__ f16   g_u2t_hi[(size_t)FH * HH];
__device__ f16   g_u2t_lo[(size_t)FH * HH];
__device__ f16   g_h1seq[(size_t)MROWS * HH];
__device__ f16   g_hs[2][BB * HH];
__device__ float g_hfp[BB * HH];
__device__ float g_b1p[FH];
__device__ float g_b2p[FH];
__device__ int   g_barcnt;
__device__ int   g_barsense;

// ---------------- ptx helpers (arch-generic) ----------------
__device__ __forceinline__ uint32_t smem_u32(const void* p) {
    return (uint32_t)__cvta_generic_to_shared(p);
}
__device__ __forceinline__ void ldsm_x4(uint32_t& r0, uint32_t& r1, uint32_t& r2,
                                        uint32_t& r3, uint32_t a) {
    asm volatile("ldmatrix.sync.aligned.m8n8.x4.shared.b16 {%0,%1,%2,%3}, [%4];"
                 : "=r"(r0), "=r"(r1), "=r"(r2), "=r"(r3) : "r"(a));
}
__device__ __forceinline__ void mma16816(float* d, uint32_t a0, uint32_t a1,
                                         uint32_t a2, uint32_t a3,
                                         uint32_t b0, uint32_t b1) {
    asm volatile(
        "mma.sync.aligned.m16n8k16.row.col.f32.f16.f16.f32 "
        "{%0,%1,%2,%3}, {%4,%5,%6,%7}, {%8,%9}, {%0,%1,%2,%3};"
        : "+f"(d[0]), "+f"(d[1]), "+f"(d[2]), "+f"(d[3])
        : "r"(a0), "r"(a1), "r"(a2), "r"(a3), "r"(b0), "r"(b1));
}
__device__ __forceinline__ void cpasync16(uint32_t s, const void* g) {
    asm volatile("cp.async.cg.shared.global [%0], [%1], 16;" :: "r"(s), "l"(g));
}
#define CP_COMMIT() asm volatile("cp.async.commit_group;" ::: "memory")
#define CP_WAIT1()  asm volatile("cp.async.wait_group 1;" ::: "memory")
#define CP_WAIT0()  asm volatile("cp.async.wait_group 0;" ::: "memory")

__device__ __forceinline__ uint32_t swz(int row, int col16) {
    return (uint32_t)(row * 128 + ((col16 ^ (row & 7)) * 16));
}

// cp.async a [R rows x 64 f16] chunk (kc-th) from K-major gmem into swizzled smem
template <int R, int NT>
__device__ __forceinline__ void cp_tile(const f16* __restrict__ src, size_t row0,
                                        int K, int kc, uint32_t sdst, int tid) {
#pragma unroll
    for (int i = tid; i < R * 8; i += NT) {
        int r = i >> 3, j = i & 7;
        cpasync16(sdst + swz(r, j), src + (row0 + r) * (size_t)K + (size_t)kc * 64 + j * 8);
    }
}

// ---------------- preprocessing ----------------
__global__ void conv_x_kernel(const float* __restrict__ x, f16* __restrict__ o, int n) {
    int i = blockIdx.x * blockDim.x + threadIdx.x;
    if (i < n) o[i] = __float2half(x[i]);
}

// W [K][4096] -> out [4096][K] K-major, gate permute n' = 4u+g (src n = g*1024+u), fp16 hi/lo
__global__ void split_wT_kernel(const float* __restrict__ W, f16* __restrict__ hiT,
                                f16* __restrict__ loT, int K) {
    __shared__ float t[32][33];
    int kb = blockIdx.y * 32, nb = blockIdx.x * 32;
    for (int r = threadIdx.y; r < 32; r += 8)
        t[r][threadIdx.x] = W[(size_t)(kb + r) * FH + nb + threadIdx.x];
    __syncthreads();
    for (int c = threadIdx.y; c < 32; c += 8) {
        int n = nb + c;
        int np = ((n & 1023) << 2) | (n >> 10);
        float v = t[threadIdx.x][c];
        f16 h = __float2half(v);
        hiT[(size_t)np * K + kb + threadIdx.x] = h;
        loT[(size_t)np * K + kb + threadIdx.x] = __float2half(v - __half2float(h));
    }
}

__global__ void permute_bias_kernel(const float* __restrict__ b, float* __restrict__ bp) {
    int np = blockIdx.x * blockDim.x + threadIdx.x;
    if (np < FH) { int u = np >> 2, g = np & 3; bp[np] = b[g * HH + u]; }
}

__global__ void zero_state_kernel() {
    int i = blockIdx.x * blockDim.x + threadIdx.x;
    if (i < (BB * HH) / 2) ((uint32_t*)g_hs[0])[i] = 0u;   // zero h as u32 pairs
    if (i == 0) { g_barcnt = 0; g_barsense = 0; }
}

// ---------------- big fp16 2-MMA GEMM: out[M][4096] = A @ (Bhi+Blo)^T + bias ----------------
// Tile 128x128, BK=64, 256 thr (8 warps: 2M x 4N), warp tile 64x32.
// REMAP=1: orow = (m&255)*64 + (m>>8)
template <int REMAP>
__global__ __launch_bounds__(256) void hgemm_kernel(
    const f16* __restrict__ A,
    const f16* __restrict__ Bhi, const f16* __restrict__ Blo,
    const float* __restrict__ bias, float* __restrict__ out, int K)
{
    extern __shared__ char smem[];
    const int tid = threadIdx.x;
    const int wid = tid >> 5, lane = tid & 31;
    const int wm = wid >> 2, wn = wid & 3;
    const int m0 = blockIdx.y * 128, n0 = blockIdx.x * 128;
    uint32_t sb = smem_u32(smem);
    const int nkc = K >> 6;

    // stage s at s*49152: A@0 (16K), Bhi@16384 (16K), Blo@32768 (16K)
    {
        uint32_t st = sb;
        cp_tile<128, 256>(A,   m0, K, 0, st, tid);
        cp_tile<128, 256>(Bhi, n0, K, 0, st + 16384, tid);
        cp_tile<128, 256>(Blo, n0, K, 0, st + 32768, tid);
        CP_COMMIT();
    }

    float acc[4][4][4] = {};   // [mt][nb][reg]

    const int a_row = wm * 64 + (lane & 7) + ((lane >> 3) & 1) * 8;  // + mt*16
    const int a_cp  = (lane >> 4) & 1;
    const int b_row = wn * 32 + (lane & 7) + ((lane >> 4) & 1) * 8;  // + nbp*16
    const int b_cp  = (lane >> 3) & 1;

    for (int kc = 0; kc < nkc; ++kc) {
        int cur = kc & 1;
        if (kc + 1 < nkc) {
            uint32_t st = sb + (uint32_t)(cur ^ 1) * 49152u;
            cp_tile<128, 256>(A,   m0, K, kc + 1, st, tid);
            cp_tile<128, 256>(Bhi, n0, K, kc + 1, st + 16384, tid);
            cp_tile<128, 256>(Blo, n0, K, kc + 1, st + 32768, tid);
            CP_COMMIT();
            CP_WAIT1();
        } else {
            CP_WAIT0();
        }
        __syncthreads();
        uint32_t stA = sb + (uint32_t)cur * 49152u;
#pragma unroll
        for (int kj = 0; kj < 4; ++kj) {
            uint32_t bh[4][2], bl[4][2];
#pragma unroll
            for (int nbp = 0; nbp < 2; ++nbp) {
                uint32_t baddr = stA + 16384 + swz(b_row + nbp * 16, kj * 2 + b_cp);
                ldsm_x4(bh[nbp * 2][0], bh[nbp * 2][1], bh[nbp * 2 + 1][0], bh[nbp * 2 + 1][1], baddr);
                ldsm_x4(bl[nbp * 2][0], bl[nbp * 2][1], bl[nbp * 2 + 1][0], bl[nbp * 2 + 1][1], baddr + 16384);
            }
#pragma unroll
            for (int mt = 0; mt < 4; ++mt) {
                uint32_t a0, a1, a2, a3;
                ldsm_x4(a0, a1, a2, a3, stA + swz(a_row + mt * 16, kj * 2 + a_cp));
#pragma unroll
                for (int nb = 0; nb < 4; ++nb) {
                    mma16816(acc[mt][nb], a0, a1, a2, a3, bh[nb][0], bh[nb][1]);
                    mma16816(acc[mt][nb], a0, a1, a2, a3, bl[nb][0], bl[nb][1]);
                }
            }
        }
        __syncthreads();
    }

#pragma unroll
    for (int mt = 0; mt < 4; ++mt) {
#pragma unroll
        for (int half_ = 0; half_ < 2; ++half_) {
            int m = m0 + wm * 64 + mt * 16 + (lane >> 2) + half_ * 8;
            size_t orow = REMAP ? ((size_t)(m & 255) * 64 + (size_t)(m >> 8)) : (size_t)m;
#pragma unroll
            for (int nb = 0; nb < 4; ++nb) {
                int n = n0 + wn * 32 + nb * 8 + 2 * (lane & 3);
                float2 v;
                v.x = acc[mt][nb][half_ * 2 + 0] + bias[n];
                v.y = acc[mt][nb][half_ * 2 + 1] + bias[n + 1];
                *(float2*)(out + orow * FH + n) = v;
            }
        }
    }
}

// ---------------- persistent LSTM layer ----------------
// 128 CTAs x 256 thr (8 warps, 4M x 2N warp tiles of 16x16). CTA owns 32 permuted cols = 8 units.
// U hi/lo (128 KB) resident in SMEM; h single fp16 streamed; c-state in SMEM.
// SMEM: Uhi@0(64K) Ulo@65536(64K) hstages@131072(2x8K) zs@147456(9216B) cs@156672(2048B)
template <int LAYER>
__global__ __launch_bounds__(256) void lstm_persist(
    const float* __restrict__ xz,
    const f16* __restrict__ Uhi, const f16* __restrict__ Ulo,
    f16* __restrict__ h0, f16* __restrict__ h1,
    f16* __restrict__ seq, float* __restrict__ hfp,
    int* __restrict__ barcnt, volatile int* __restrict__ barsense)
{
    extern __shared__ char smem[];
    const int tid = threadIdx.x;
    const int wid = tid >> 5, lane = tid & 31;
    const int wm = wid & 3, wn = wid >> 2;
    const int n0 = blockIdx.x * 32;
    const int u0 = blockIdx.x * 8;
    uint32_t sb = smem_u32(smem);
    float* zs = (float*)(smem + 147456);
    float* cs = (float*)(smem + 156672);

    // load U tile once: 16 kblocks x (32 rows x 64 k fp16 = 4KB)
    for (int i = tid; i < 4096; i += 256) {
        int kb = i >> 8, r = (i >> 3) & 31, j = i & 7;
        size_t goff = (size_t)(n0 + r) * HH + kb * 64 + j * 8;
        uint32_t off = (uint32_t)(kb * 4096) + swz(r, j);
        *(uint4*)(smem + off)         = *(const uint4*)(Uhi + goff);
        *(uint4*)(smem + 65536 + off) = *(const uint4*)(Ulo + goff);
    }
    for (int i = tid; i < 512; i += 256) cs[i] = 0.0f;

    int sense = 0;
    const int a_row = wm * 16 + (lane & 7) + ((lane >> 3) & 1) * 8;
    const int a_cp  = (lane >> 4) & 1;
    const int b_row = wn * 16 + (lane & 7) + ((lane >> 4) & 1) * 8;
    const int b_cp  = (lane >> 3) & 1;
    __syncthreads();

    for (int t = 0; t < TT; ++t) {
        const f16* hin = (t & 1) ? h1 : h0;
        f16* hout = (t & 1) ? h0 : h1;
        const float* xzt = xz + (size_t)t * BB * FH;

        float acc[2][4] = {};   // [nb][reg]

        {   // prime stage 0 with h chunk 0 (64 rows x 64 k fp16 = 8KB)
            uint32_t s0 = sb + 131072;
#pragma unroll
            for (int i = tid; i < 512; i += 256) {
                int r = i >> 3, j = i & 7;
                cpasync16(s0 + swz(r, j), hin + (size_t)r * HH + j * 8);
            }
            CP_COMMIT();
        }
        for (int kc = 0; kc < 16; ++kc) {
            int cur = kc & 1;
            if (kc + 1 < 16) {
                uint32_t sn = sb + 131072 + (uint32_t)(cur ^ 1) * 8192u;
#pragma unroll
                for (int i = tid; i < 512; i += 256) {
                    int r = i >> 3, j = i & 7;
                    cpasync16(sn + swz(r, j), hin + (size_t)r * HH + (kc + 1) * 64 + j * 8);
                }
                CP_COMMIT();
                CP_WAIT1();
            } else {
                CP_WAIT0();
            }
            __syncthreads();
            uint32_t hA = sb + 131072 + (uint32_t)cur * 8192u;
            uint32_t uB = sb + (uint32_t)kc * 4096u;
#pragma unroll
            for (int kj = 0; kj < 4; ++kj) {
                uint32_t a0, a1, a2, a3;
                ldsm_x4(a0, a1, a2, a3, hA + swz(a_row, kj * 2 + a_cp));
                uint32_t bh[2][2], bl[2][2];
                uint32_t baddr = uB + swz(b_row, kj * 2 + b_cp);
                ldsm_x4(bh[0][0], bh[0][1], bh[1][0], bh[1][1], baddr);
                ldsm_x4(bl[0][0], bl[0][1], bl[1][0], bl[1][1], baddr + 65536);
                mma16816(acc[0], a0, a1, a2, a3, bh[0][0], bh[0][1]);
                mma16816(acc[1], a0, a1, a2, a3, bh[1][0], bh[1][1]);
                mma16816(acc[0], a0, a1, a2, a3, bl[0][0], bl[0][1]);
                mma16816(acc[1], a0, a1, a2, a3, bl[1][0], bl[1][1]);
            }
            __syncthreads();
        }
        // write z tile to smem (stride 36 floats)
        {
            int m = wm * 16 + (lane >> 2);
            int nbase = wn * 16 + 2 * (lane & 3);
#pragma unroll
            for (int nb = 0; nb < 2; ++nb) {
                int nn = nbase + nb * 8;
                zs[m * 36 + nn]           = acc[nb][0];
                zs[m * 36 + nn + 1]       = acc[nb][1];
                zs[(m + 8) * 36 + nn]     = acc[nb][2];
                zs[(m + 8) * 36 + nn + 1] = acc[nb][3];
            }
        }
        __syncthreads();
        // epilogue: thread -> (b = tid/4, 2 units)
        {
            int b = tid >> 2;
            int uu0 = (tid & 3) * 2;
            const float* xzb = xzt + (size_t)b * FH + n0;
            const float* zrow = zs + b * 36;
#pragma unroll
            for (int q = 0; q < 2; ++q) {
                int uu = uu0 + q;
                float4 xv = *(const float4*)(xzb + uu * 4);
                float zi = zrow[uu * 4 + 0] + xv.x;
                float zf = zrow[uu * 4 + 1] + xv.y;
                float zg = zrow[uu * 4 + 2] + xv.z;
                float zo = zrow[uu * 4 + 3] + xv.w;
                float si = 1.0f / (1.0f + __expf(-zi));
                float sf = 1.0f / (1.0f + __expf(-zf));
                float so = 1.0f / (1.0f + __expf(-zo));
                float tg = 1.0f - 2.0f / (__expf(2.0f * zg) + 1.0f);
                int ci = b * 8 + uu;
                float cn = sf * cs[ci] + si * tg;
                cs[ci] = cn;
                float tc = 1.0f - 2.0f / (__expf(2.0f * cn) + 1.0f);
                float hn = so * tc;
                hout[(size_t)b * HH + u0 + uu] = __float2half(hn);
                if (LAYER == 1) {
                    seq[(size_t)t * (BB * HH) + b * HH + u0 + uu] = __float2half(hn);
                } else if (t == TT - 1) {
                    hfp[b * HH + u0 + uu] = hn;
                }
            }
        }
        // grid barrier (sense-reversal; 128 resident CTAs)
        __syncthreads();
        if (tid == 0) {
            int s = sense ^ 1;
            __threadfence();
            if (atomicAdd(barcnt, 1) == 127) {
                *barcnt = 0;
                __threadfence();
                *barsense = s;
            } else {
                while (*barsense != s) { __nanosleep(40); }
            }
            __threadfence();
        }
        sense ^= 1;
        __syncthreads();
    }
}

// ---------------- fp32 GEMM for the tiny final dense ----------------
__global__ __launch_bounds__(256) void gemm64_kernel(
    const float* __restrict__ A, const float* __restrict__ Wt,
    const float* __restrict__ bias, float* __restrict__ Cout,
    int K, int N)
{
    __shared__ float As[2][16 * 68];
    __shared__ float Bs[2][16 * 64];
    const int m0 = blockIdx.y * 64;
    const int n0 = blockIdx.x * 64;
    const int tid = threadIdx.x;
    const int tn = tid & 15;
    const int tm = tid >> 4;
    const int am = tid >> 2;
    const int ak = (tid & 3) * 4;
    const int bk = tid >> 4;
    const int bn = (tid & 15) * 4;
    const float* Aptr = A + (size_t)(m0 + am) * K + ak;
    const float* Bptr = Wt + (size_t)bk * N + n0 + bn;
    float acc[4][4] = {};
    float4 areg, breg;
    const int nchunk = K / 16;
    areg = *(const float4*)(Aptr);
    breg = *(const float4*)(Bptr);
    {
        float* as = As[0]; float* bs = Bs[0];
        as[(ak + 0) * 68 + am] = areg.x; as[(ak + 1) * 68 + am] = areg.y;
        as[(ak + 2) * 68 + am] = areg.z; as[(ak + 3) * 68 + am] = areg.w;
        *(float4*)&bs[bk * 64 + bn] = breg;
    }
    __syncthreads();
    for (int c = 0; c < nchunk; ++c) {
        if (c + 1 < nchunk) {
            areg = *(const float4*)(Aptr + (c + 1) * 16);
            breg = *(const float4*)(Bptr + (size_t)(c + 1) * 16 * N);
        }
        const float* as = As[c & 1];
        const float* bs = Bs[c & 1];
#pragma unroll
        for (int k = 0; k < 16; ++k) {
            float4 a4 = *(const float4*)&as[k * 68 + 4 * tm];
            float4 b4 = *(const float4*)&bs[k * 64 + 4 * tn];
            acc[0][0] += a4.x * b4.x; acc[0][1] += a4.x * b4.y;
            acc[0][2] += a4.x * b4.z; acc[0][3] += a4.x * b4.w;
            acc[1][0] += a4.y * b4.x; acc[1][1] += a4.y * b4.y;
            acc[1][2] += a4.y * b4.z; acc[1][3] += a4.y * b4.w;
            acc[2][0] += a4.z * b4.x; acc[2][1] += a4.z * b4.y;
            acc[2][2] += a4.z * b4.z; acc[2][3] += a4.z * b4.w;
            acc[3][0] += a4.w * b4.x; acc[3][1] += a4.w * b4.y;
            acc[3][2] += a4.w * b4.z; acc[3][3] += a4.w * b4.w;
        }
        if (c + 1 < nchunk) {
            float* asw = As[(c + 1) & 1]; float* bsw = Bs[(c + 1) & 1];
            asw[(ak + 0) * 68 + am] = areg.x; asw[(ak + 1) * 68 + am] = areg.y;
            asw[(ak + 2) * 68 + am] = areg.z; asw[(ak + 3) * 68 + am] = areg.w;
            *(float4*)&bsw[bk * 64 + bn] = breg;
        }
        __syncthreads();
    }
#pragma unroll
    for (int i = 0; i < 4; ++i) {
        int m = m0 + 4 * tm + i;
        float4 v;
        v.x = acc[i][0] + bias[n0 + 4 * tn + 0];
        v.y = acc[i][1] + bias[n0 + 4 * tn + 1];
        v.z = acc[i][2] + bias[n0 + 4 * tn + 2];
        v.w = acc[i][3] + bias[n0 + 4 * tn + 3];
        *(float4*)&Cout[(size_t)m * N + n0 + 4 * tn] = v;
    }
}

// ---------------- launch ----------------
extern "C" void kernel_launch(void* const* d_in, const int* in_sizes, int n_in,
                              void* d_out, int out_size)
{
    const float* x  = (const float*)d_in[0];
    const float* W1 = (const float*)d_in[1];
    const float* U1 = (const float*)d_in[2];
    const float* b1 = (const float*)d_in[3];
    const float* W2 = (const float*)d_in[4];
    const float* U2 = (const float*)d_in[5];
    const float* b2 = (const float*)d_in[6];
    const float* Wd = (const float*)d_in[7];
    const float* bd = (const float*)d_in[8];
    float* out = (float*)d_out;

#define SYM(v, s) do { void* p_; cudaGetSymbolAddress(&p_, s); v = (decltype(v))p_; } while (0)
    float *xz, *b1p, *b2p, *hfp;
    f16 *x16, *w1h, *w1l, *u1h, *u1l, *w2h, *w2l, *u2h, *u2l, *h1s, *hs;
    int* barc; int* bars;
    SYM(xz, g_xz); SYM(b1p, g_b1p); SYM(b2p, g_b2p); SYM(hfp, g_hfp);
    SYM(x16, g_x16);
    SYM(w1h, g_w1t_hi); SYM(w1l, g_w1t_lo); SYM(u1h, g_u1t_hi); SYM(u1l, g_u1t_lo);
    SYM(w2h, g_w2t_hi); SYM(w2l, g_w2t_lo); SYM(u2h, g_u2t_hi); SYM(u2l, g_u2t_lo);
    SYM(h1s, g_h1seq); SYM(hs, g_hs);
    SYM(barc, g_barcnt); SYM(bars, g_barsense);
#undef SYM

    const int GEMM_SMEM = 2 * 49152;    // 98304
    const int PERS_SMEM = 158720;
    cudaFuncSetAttribute(hgemm_kernel<0>, cudaFuncAttributeMaxDynamicSharedMemorySize, GEMM_SMEM);
    cudaFuncSetAttribute(hgemm_kernel<1>, cudaFuncAttributeMaxDynamicSharedMemorySize, GEMM_SMEM);
    cudaFuncSetAttribute(lstm_persist<1>, cudaFuncAttributeMaxDynamicSharedMemorySize, PERS_SMEM);
    cudaFuncSetAttribute(lstm_persist<2>, cudaFuncAttributeMaxDynamicSharedMemorySize, PERS_SMEM);

    // preprocessing
    conv_x_kernel<<<(MROWS * DD + 255) / 256, 256>>>(x, x16, MROWS * DD);
    split_wT_kernel<<<dim3(FH / 32, DD / 32), dim3(32, 8)>>>(W1, w1h, w1l, DD);
    split_wT_kernel<<<dim3(FH / 32, HH / 32), dim3(32, 8)>>>(U1, u1h, u1l, HH);
    split_wT_kernel<<<dim3(FH / 32, HH / 32), dim3(32, 8)>>>(W2, w2h, w2l, HH);
    split_wT_kernel<<<dim3(FH / 32, HH / 32), dim3(32, 8)>>>(U2, u2h, u2l, HH);
    permute_bias_kernel<<<FH / 256, 256>>>(b1, b1p);
    permute_bias_kernel<<<FH / 256, 256>>>(b2, b2p);

    const dim3 ggrid(FH / 128, MROWS / 128);   // (32, 128)

    // layer 1: xz = x @ W1p + b1p  (rows remapped to [t][b])
    hgemm_kernel<1><<<ggrid, 256, GEMM_SMEM>>>(x16, w1h, w1l, b1p, xz, DD);
    zero_state_kernel<<<(BB * HH + 255) / 256, 256>>>();
    lstm_persist<1><<<128, 256, PERS_SMEM>>>(
        xz, u1h, u1l,
        hs, hs + BB * HH,
        h1s, (float*)0, barc, bars);

    // layer 2: xz = h1seq @ W2p + b2p  (rows already [t][b])
    hgemm_kernel<0><<<ggrid, 256, GEMM_SMEM>>>(h1s, w2h, w2l, b2p, xz, HH);
    zero_state_kernel<<<(BB * HH + 255) / 256, 256>>>();
    lstm_persist<2><<<128, 256, PERS_SMEM>>>(
        xz, u2h, u2l,
        hs, hs + BB * HH,
        (f16*)0, hfp, barc, bars);

    // final dense: out = h_last @ Wd + bd
    gemm64_kernel<<<dim3(OO / 64, BB / 64), 256>>>(hfp, Wd, bd, out, HH, OO);
}

// round 16
// speedup vs baseline: 5.3692x; 1.0600x over previous
#include <cuda_runtime.h>
#include <cuda_fp16.h>
#include <math.h>
#include <stdint.h>

typedef __half f16;

#define BB 64
#define TT 256
#define DD 512
#define HH 1024
#define FH 4096
#define OO 512
#define MROWS (BB*TT)

// ---------------- scratch (device globals; no allocation) ----------------
__device__ float g_xz[(size_t)MROWS * FH];
__device__ f16   g_x16[(size_t)MROWS * DD];
__device__ f16   g_w1t_hi[(size_t)FH * DD];
__device__ f16   g_w1t_lo[(size_t)FH * DD];
__device__ f16   g_u1t_hi[(size_t)FH * HH];
__device__ f16   g_u1t_lo[(size_t)FH * HH];
__device__ f16   g_w2t_hi[(size_t)FH * HH];
__device__ f16   g_w2t_lo[(size_t)FH * HH];
__device__ f16   g_u2t_hi[(size_t)FH * HH];
__device__ f16   g_u2t_lo[(size_t)FH * HH];
__device__ f16   g_h1seq[(size_t)MROWS * HH];
__device__ f16   g_hs[2][BB * HH];
__device__ float g_hfp[BB * HH];
__device__ float g_b1p[FH];
__device__ float g_b2p[FH];
__device__ int   g_barcnt;
__device__ int   g_barsense;

// ---------------- ptx helpers (arch-generic) ----------------
__device__ __forceinline__ uint32_t smem_u32(const void* p) {
    return (uint32_t)__cvta_generic_to_shared(p);
}
__device__ __forceinline__ void ldsm_x4(uint32_t& r0, uint32_t& r1, uint32_t& r2,
                                        uint32_t& r3, uint32_t a) {
    asm volatile("ldmatrix.sync.aligned.m8n8.x4.shared.b16 {%0,%1,%2,%3}, [%4];"
                 : "=r"(r0), "=r"(r1), "=r"(r2), "=r"(r3) : "r"(a));
}
__device__ __forceinline__ void mma16816(float* d, uint32_t a0, uint32_t a1,
                                         uint32_t a2, uint32_t a3,
                                         uint32_t b0, uint32_t b1) {
    asm volatile(
        "mma.sync.aligned.m16n8k16.row.col.f32.f16.f16.f32 "
        "{%0,%1,%2,%3}, {%4,%5,%6,%7}, {%8,%9}, {%0,%1,%2,%3};"
        : "+f"(d[0]), "+f"(d[1]), "+f"(d[2]), "+f"(d[3])
        : "r"(a0), "r"(a1), "r"(a2), "r"(a3), "r"(b0), "r"(b1));
}
__device__ __forceinline__ void cpasync16(uint32_t s, const void* g) {
    asm volatile("cp.async.cg.shared.global [%0], [%1], 16;" :: "r"(s), "l"(g));
}
#define CP_COMMIT() asm volatile("cp.async.commit_group;" ::: "memory")
#define CP_WAIT1()  asm volatile("cp.async.wait_group 1;" ::: "memory")
#define CP_WAIT0()  asm volatile("cp.async.wait_group 0;" ::: "memory")

__device__ __forceinline__ float tanha(float x) {
    float y;
    asm("tanh.approx.f32 %0, %1;" : "=f"(y) : "f"(x));
    return y;
}

__device__ __forceinline__ uint32_t swz(int row, int col16) {
    return (uint32_t)(row * 128 + ((col16 ^ (row & 7)) * 16));
}

// cp.async a [R rows x 64 f16] chunk (kc-th) from K-major gmem into swizzled smem
template <int R, int NT>
__device__ __forceinline__ void cp_tile(const f16* __restrict__ src, size_t row0,
                                        int K, int kc, uint32_t sdst, int tid) {
#pragma unroll
    for (int i = tid; i < R * 8; i += NT) {
        int r = i >> 3, j = i & 7;
        cpasync16(sdst + swz(r, j), src + (row0 + r) * (size_t)K + (size_t)kc * 64 + j * 8);
    }
}

// ---------------- preprocessing ----------------
__global__ void conv_x_kernel(const float* __restrict__ x, f16* __restrict__ o, int n) {
    int i = blockIdx.x * blockDim.x + threadIdx.x;
    if (i < n) o[i] = __float2half(x[i]);
}

// W [K][4096] -> out [4096][K] K-major, gate permute n' = 4u+g (src n = g*1024+u), fp16 hi/lo
__global__ void split_wT_kernel(const float* __restrict__ W, f16* __restrict__ hiT,
                                f16* __restrict__ loT, int K) {
    __shared__ float t[32][33];
    int kb = blockIdx.y * 32, nb = blockIdx.x * 32;
    for (int r = threadIdx.y; r < 32; r += 8)
        t[r][threadIdx.x] = W[(size_t)(kb + r) * FH + nb + threadIdx.x];
    __syncthreads();
    for (int c = threadIdx.y; c < 32; c += 8) {
        int n = nb + c;
        int np = ((n & 1023) << 2) | (n >> 10);
        float v = t[threadIdx.x][c];
        f16 h = __float2half(v);
        hiT[(size_t)np * K + kb + threadIdx.x] = h;
        loT[(size_t)np * K + kb + threadIdx.x] = __float2half(v - __half2float(h));
    }
}

__global__ void permute_bias_kernel(const float* __restrict__ b, float* __restrict__ bp) {
    int np = blockIdx.x * blockDim.x + threadIdx.x;
    if (np < FH) { int u = np >> 2, g = np & 3; bp[np] = b[g * HH + u]; }
}

__global__ void zero_state_kernel() {
    int i = blockIdx.x * blockDim.x + threadIdx.x;
    if (i < (BB * HH) / 2) ((uint32_t*)g_hs[0])[i] = 0u;   // zero h as u32 pairs
    if (i == 0) { g_barcnt = 0; g_barsense = 0; }
}

// ---------------- big fp16 2-MMA GEMM: out[M][4096] = A @ (Bhi+Blo)^T + bias ----------------
// Tile 128x128, BK=64, 256 thr (8 warps: 2M x 4N), warp tile 64x32.
// REMAP=1: orow = (m&255)*64 + (m>>8)
template <int REMAP>
__global__ __launch_bounds__(256) void hgemm_kernel(
    const f16* __restrict__ A,
    const f16* __restrict__ Bhi, const f16* __restrict__ Blo,
    const float* __restrict__ bias, float* __restrict__ out, int K)
{
    extern __shared__ char smem[];
    const int tid = threadIdx.x;
    const int wid = tid >> 5, lane = tid & 31;
    const int wm = wid >> 2, wn = wid & 3;
    const int m0 = blockIdx.y * 128, n0 = blockIdx.x * 128;
    uint32_t sb = smem_u32(smem);
    const int nkc = K >> 6;

    // stage s at s*49152: A@0 (16K), Bhi@16384 (16K), Blo@32768 (16K)
    {
        uint32_t st = sb;
        cp_tile<128, 256>(A,   m0, K, 0, st, tid);
        cp_tile<128, 256>(Bhi, n0, K, 0, st + 16384, tid);
        cp_tile<128, 256>(Blo, n0, K, 0, st + 32768, tid);
        CP_COMMIT();
    }

    float acc[4][4][4] = {};   // [mt][nb][reg]

    const int a_row = wm * 64 + (lane & 7) + ((lane >> 3) & 1) * 8;  // + mt*16
    const int a_cp  = (lane >> 4) & 1;
    const int b_row = wn * 32 + (lane & 7) + ((lane >> 4) & 1) * 8;  // + nbp*16
    const int b_cp  = (lane >> 3) & 1;

    for (int kc = 0; kc < nkc; ++kc) {
        int cur = kc & 1;
        if (kc + 1 < nkc) {
            uint32_t st = sb + (uint32_t)(cur ^ 1) * 49152u;
            cp_tile<128, 256>(A,   m0, K, kc + 1, st, tid);
            cp_tile<128, 256>(Bhi, n0, K, kc + 1, st + 16384, tid);
            cp_tile<128, 256>(Blo, n0, K, kc + 1, st + 32768, tid);
            CP_COMMIT();
            CP_WAIT1();
        } else {
            CP_WAIT0();
        }
        __syncthreads();
        uint32_t stA = sb + (uint32_t)cur * 49152u;
#pragma unroll
        for (int kj = 0; kj < 4; ++kj) {
            uint32_t bh[4][2], bl[4][2];
#pragma unroll
            for (int nbp = 0; nbp < 2; ++nbp) {
                uint32_t baddr = stA + 16384 + swz(b_row + nbp * 16, kj * 2 + b_cp);
                ldsm_x4(bh[nbp * 2][0], bh[nbp * 2][1], bh[nbp * 2 + 1][0], bh[nbp * 2 + 1][1], baddr);
                ldsm_x4(bl[nbp * 2][0], bl[nbp * 2][1], bl[nbp * 2 + 1][0], bl[nbp * 2 + 1][1], baddr + 16384);
            }
#pragma unroll
            for (int mt = 0; mt < 4; ++mt) {
                uint32_t a0, a1, a2, a3;
                ldsm_x4(a0, a1, a2, a3, stA + swz(a_row + mt * 16, kj * 2 + a_cp));
#pragma unroll
                for (int nb = 0; nb < 4; ++nb) {
                    mma16816(acc[mt][nb], a0, a1, a2, a3, bh[nb][0], bh[nb][1]);
                    mma16816(acc[mt][nb], a0, a1, a2, a3, bl[nb][0], bl[nb][1]);
                }
            }
        }
        __syncthreads();
    }

#pragma unroll
    for (int mt = 0; mt < 4; ++mt) {
#pragma unroll
        for (int half_ = 0; half_ < 2; ++half_) {
            int m = m0 + wm * 64 + mt * 16 + (lane >> 2) + half_ * 8;
            size_t orow = REMAP ? ((size_t)(m & 255) * 64 + (size_t)(m >> 8)) : (size_t)m;
#pragma unroll
            for (int nb = 0; nb < 4; ++nb) {
                int n = n0 + wn * 32 + nb * 8 + 2 * (lane & 3);
                float2 v;
                v.x = acc[mt][nb][half_ * 2 + 0] + bias[n];
                v.y = acc[mt][nb][half_ * 2 + 1] + bias[n + 1];
                *(float2*)(out + orow * FH + n) = v;
            }
        }
    }
}

// ---------------- persistent LSTM layer (R11-proven structure; tanh.approx epilogue) ----------------
// 128 CTAs x 256 thr (8 warps, 4M x 2N warp tiles of 16x16). CTA owns 32 permuted cols = 8 units.
// U hi/lo (128 KB) resident in SMEM; h single fp16 streamed; c-state in SMEM.
// SMEM: Uhi@0(64K) Ulo@65536(64K) hstages@131072(2x8K) zs@147456(9216B) cs@156672(2048B)
template <int LAYER>
__global__ __launch_bounds__(256) void lstm_persist(
    const float* __restrict__ xz,
    const f16* __restrict__ Uhi, const f16* __restrict__ Ulo,
    f16* __restrict__ h0, f16* __restrict__ h1,
    f16* __restrict__ seq, float* __restrict__ hfp,
    int* __restrict__ barcnt, volatile int* __restrict__ barsense)
{
    extern __shared__ char smem[];
    const int tid = threadIdx.x;
    const int wid = tid >> 5, lane = tid & 31;
    const int wm = wid & 3, wn = wid >> 2;
    const int n0 = blockIdx.x * 32;
    const int u0 = blockIdx.x * 8;
    uint32_t sb = smem_u32(smem);
    float* zs = (float*)(smem + 147456);
    float* cs = (float*)(smem + 156672);

    // load U tile once: 16 kblocks x (32 rows x 64 k fp16 = 4KB)
    for (int i = tid; i < 4096; i += 256) {
        int kb = i >> 8, r = (i >> 3) & 31, j = i & 7;
        size_t goff = (size_t)(n0 + r) * HH + kb * 64 + j * 8;
        uint32_t off = (uint32_t)(kb * 4096) + swz(r, j);
        *(uint4*)(smem + off)         = *(const uint4*)(Uhi + goff);
        *(uint4*)(smem + 65536 + off) = *(const uint4*)(Ulo + goff);
    }
    for (int i = tid; i < 512; i += 256) cs[i] = 0.0f;

    int sense = 0;
    const int a_row = wm * 16 + (lane & 7) + ((lane >> 3) & 1) * 8;
    const int a_cp  = (lane >> 4) & 1;
    const int b_row = wn * 16 + (lane & 7) + ((lane >> 4) & 1) * 8;
    const int b_cp  = (lane >> 3) & 1;
    __syncthreads();

    for (int t = 0; t < TT; ++t) {
        const f16* hin = (t & 1) ? h1 : h0;
        f16* hout = (t & 1) ? h0 : h1;
        const float* xzt = xz + (size_t)t * BB * FH;

        float acc[2][4] = {};   // [nb][reg]

        {   // prime stage 0 with h chunk 0 (64 rows x 64 k fp16 = 8KB)
            uint32_t s0 = sb + 131072;
#pragma unroll
            for (int i = tid; i < 512; i += 256) {
                int r = i >> 3, j = i & 7;
                cpasync16(s0 + swz(r, j), hin + (size_t)r * HH + j * 8);
            }
            CP_COMMIT();
        }
        for (int kc = 0; kc < 16; ++kc) {
            int cur = kc & 1;
            if (kc + 1 < 16) {
                uint32_t sn = sb + 131072 + (uint32_t)(cur ^ 1) * 8192u;
#pragma unroll
                for (int i = tid; i < 512; i += 256) {
                    int r = i >> 3, j = i & 7;
                    cpasync16(sn + swz(r, j), hin + (size_t)r * HH + (kc + 1) * 64 + j * 8);
                }
                CP_COMMIT();
                CP_WAIT1();
            } else {
                CP_WAIT0();
            }
            __syncthreads();
            uint32_t hA = sb + 131072 + (uint32_t)cur * 8192u;
            uint32_t uB = sb + (uint32_t)kc * 4096u;
#pragma unroll
            for (int kj = 0; kj < 4; ++kj) {
                uint32_t a0, a1, a2, a3;
                ldsm_x4(a0, a1, a2, a3, hA + swz(a_row, kj * 2 + a_cp));
                uint32_t bh[2][2], bl[2][2];
                uint32_t baddr = uB + swz(b_row, kj * 2 + b_cp);
                ldsm_x4(bh[0][0], bh[0][1], bh[1][0], bh[1][1], baddr);
                ldsm_x4(bl[0][0], bl[0][1], bl[1][0], bl[1][1], baddr + 65536);
                mma16816(acc[0], a0, a1, a2, a3, bh[0][0], bh[0][1]);
                mma16816(acc[1], a0, a1, a2, a3, bh[1][0], bh[1][1]);
                mma16816(acc[0], a0, a1, a2, a3, bl[0][0], bl[0][1]);
                mma16816(acc[1], a0, a1, a2, a3, bl[1][0], bl[1][1]);
            }
            __syncthreads();
        }
        // write z tile to smem (stride 36 floats)
        {
            int m = wm * 16 + (lane >> 2);
            int nbase = wn * 16 + 2 * (lane & 3);
#pragma unroll
            for (int nb = 0; nb < 2; ++nb) {
                int nn = nbase + nb * 8;
                zs[m * 36 + nn]           = acc[nb][0];
                zs[m * 36 + nn + 1]       = acc[nb][1];
                zs[(m + 8) * 36 + nn]     = acc[nb][2];
                zs[(m + 8) * 36 + nn + 1] = acc[nb][3];
            }
        }
        __syncthreads();
        // epilogue: thread -> (b = tid/4, 2 units); tanh.approx activations
        {
            int b = tid >> 2;
            int uu0 = (tid & 3) * 2;
            const float* xzb = xzt + (size_t)b * FH + n0;
            const float* zrow = zs + b * 36;
#pragma unroll
            for (int q = 0; q < 2; ++q) {
                int uu = uu0 + q;
                float4 xv = *(const float4*)(xzb + uu * 4);
                float zi = zrow[uu * 4 + 0] + xv.x;
                float zf = zrow[uu * 4 + 1] + xv.y;
                float zg = zrow[uu * 4 + 2] + xv.z;
                float zo = zrow[uu * 4 + 3] + xv.w;
                float si = 0.5f * tanha(0.5f * zi) + 0.5f;
                float sf = 0.5f * tanha(0.5f * zf) + 0.5f;
                float so = 0.5f * tanha(0.5f * zo) + 0.5f;
                float tg = tanha(zg);
                int ci = b * 8 + uu;
                float cn = sf * cs[ci] + si * tg;
                cs[ci] = cn;
                float hn = so * tanha(cn);
                hout[(size_t)b * HH + u0 + uu] = __float2half(hn);
                if (LAYER == 1) {
                    seq[(size_t)t * (BB * HH) + b * HH + u0 + uu] = __float2half(hn);
                } else if (t == TT - 1) {
                    hfp[b * HH + u0 + uu] = hn;
                }
            }
        }
        // grid barrier (sense-reversal; 128 resident CTAs)
        __syncthreads();
        if (tid == 0) {
            int s = sense ^ 1;
            __threadfence();
            if (atomicAdd(barcnt, 1) == 127) {
                *barcnt = 0;
                __threadfence();
                *barsense = s;
            } else {
                while (*barsense != s) { __nanosleep(40); }
            }
            __threadfence();
        }
        sense ^= 1;
        __syncthreads();
    }
}

// ---------------- fp32 GEMM for the tiny final dense ----------------
__global__ __launch_bounds__(256) void gemm64_kernel(
    const float* __restrict__ A, const float* __restrict__ Wt,
    const float* __restrict__ bias, float* __restrict__ Cout,
    int K, int N)
{
    __shared__ float As[2][16 * 68];
    __shared__ float Bs[2][16 * 64];
    const int m0 = blockIdx.y * 64;
    const int n0 = blockIdx.x * 64;
    const int tid = threadIdx.x;
    const int tn = tid & 15;
    const int tm = tid >> 4;
    const int am = tid >> 2;
    const int ak = (tid & 3) * 4;
    const int bk = tid >> 4;
    const int bn = (tid & 15) * 4;
    const float* Aptr = A + (size_t)(m0 + am) * K + ak;
    const float* Bptr = Wt + (size_t)bk * N + n0 + bn;
    float acc[4][4] = {};
    float4 areg, breg;
    const int nchunk = K / 16;
    areg = *(const float4*)(Aptr);
    breg = *(const float4*)(Bptr);
    {
        float* as = As[0]; float* bs = Bs[0];
        as[(ak + 0) * 68 + am] = areg.x; as[(ak + 1) * 68 + am] = areg.y;
        as[(ak + 2) * 68 + am] = areg.z; as[(ak + 3) * 68 + am] = areg.w;
        *(float4*)&bs[bk * 64 + bn] = breg;
    }
    __syncthreads();
    for (int c = 0; c < nchunk; ++c) {
        if (c + 1 < nchunk) {
            areg = *(const float4*)(Aptr + (c + 1) * 16);
            breg = *(const float4*)(Bptr + (size_t)(c + 1) * 16 * N);
        }
        const float* as = As[c & 1];
        const float* bs = Bs[c & 1];
#pragma unroll
        for (int k = 0; k < 16; ++k) {
            float4 a4 = *(const float4*)&as[k * 68 + 4 * tm];
            float4 b4 = *(const float4*)&bs[k * 64 + 4 * tn];
            acc[0][0] += a4.x * b4.x; acc[0][1] += a4.x * b4.y;
            acc[0][2] += a4.x * b4.z; acc[0][3] += a4.x * b4.w;
            acc[1][0] += a4.y * b4.x; acc[1][1] += a4.y * b4.y;
            acc[1][2] += a4.y * b4.z; acc[1][3] += a4.y * b4.w;
            acc[2][0] += a4.z * b4.x; acc[2][1] += a4.z * b4.y;
            acc[2][2] += a4.z * b4.z; acc[2][3] += a4.z * b4.w;
            acc[3][0] += a4.w * b4.x; acc[3][1] += a4.w * b4.y;
            acc[3][2] += a4.w * b4.z; acc[3][3] += a4.w * b4.w;
        }
        if (c + 1 < nchunk) {
            float* asw = As[(c + 1) & 1]; float* bsw = Bs[(c + 1) & 1];
            asw[(ak + 0) * 68 + am] = areg.x; asw[(ak + 1) * 68 + am] = areg.y;
            asw[(ak + 2) * 68 + am] = areg.z; asw[(ak + 3) * 68 + am] = areg.w;
            *(float4*)&bsw[bk * 64 + bn] = breg;
        }
        __syncthreads();
    }
#pragma unroll
    for (int i = 0; i < 4; ++i) {
        int m = m0 + 4 * tm + i;
        float4 v;
        v.x = acc[i][0] + bias[n0 + 4 * tn + 0];
        v.y = acc[i][1] + bias[n0 + 4 * tn + 1];
        v.z = acc[i][2] + bias[n0 + 4 * tn + 2];
        v.w = acc[i][3] + bias[n0 + 4 * tn + 3];
        *(float4*)&Cout[(size_t)m * N + n0 + 4 * tn] = v;
    }
}

// ---------------- launch ----------------
extern "C" void kernel_launch(void* const* d_in, const int* in_sizes, int n_in,
                              void* d_out, int out_size)
{
    const float* x  = (const float*)d_in[0];
    const float* W1 = (const float*)d_in[1];
    const float* U1 = (const float*)d_in[2];
    const float* b1 = (const float*)d_in[3];
    const float* W2 = (const float*)d_in[4];
    const float* U2 = (const float*)d_in[5];
    const float* b2 = (const float*)d_in[6];
    const float* Wd = (const float*)d_in[7];
    const float* bd = (const float*)d_in[8];
    float* out = (float*)d_out;

#define SYM(v, s) do { void* p_; cudaGetSymbolAddress(&p_, s); v = (decltype(v))p_; } while (0)
    float *xz, *b1p, *b2p, *hfp;
    f16 *x16, *w1h, *w1l, *u1h, *u1l, *w2h, *w2l, *u2h, *u2l, *h1s, *hs;
    int* barc; int* bars;
    SYM(xz, g_xz); SYM(b1p, g_b1p); SYM(b2p, g_b2p); SYM(hfp, g_hfp);
    SYM(x16, g_x16);
    SYM(w1h, g_w1t_hi); SYM(w1l, g_w1t_lo); SYM(u1h, g_u1t_hi); SYM(u1l, g_u1t_lo);
    SYM(w2h, g_w2t_hi); SYM(w2l, g_w2t_lo); SYM(u2h, g_u2t_hi); SYM(u2l, g_u2t_lo);
    SYM(h1s, g_h1seq); SYM(hs, g_hs);
    SYM(barc, g_barcnt); SYM(bars, g_barsense);
#undef SYM

    const int GEMM_SMEM = 2 * 49152;    // 98304
    const int PERS_SMEM = 158720;
    cudaFuncSetAttribute(hgemm_kernel<0>, cudaFuncAttributeMaxDynamicSharedMemorySize, GEMM_SMEM);
    cudaFuncSetAttribute(hgemm_kernel<1>, cudaFuncAttributeMaxDynamicSharedMemorySize, GEMM_SMEM);
    cudaFuncSetAttribute(lstm_persist<1>, cudaFuncAttributeMaxDynamicSharedMemorySize, PERS_SMEM);
    cudaFuncSetAttribute(lstm_persist<2>, cudaFuncAttributeMaxDynamicSharedMemorySize, PERS_SMEM);

    // preprocessing
    conv_x_kernel<<<(MROWS * DD + 255) / 256, 256>>>(x, x16, MROWS * DD);
    split_wT_kernel<<<dim3(FH / 32, DD / 32), dim3(32, 8)>>>(W1, w1h, w1l, DD);
    split_wT_kernel<<<dim3(FH / 32, HH / 32), dim3(32, 8)>>>(U1, u1h, u1l, HH);
    split_wT_kernel<<<dim3(FH / 32, HH / 32), dim3(32, 8)>>>(W2, w2h, w2l, HH);
    split_wT_kernel<<<dim3(FH / 32, HH / 32), dim3(32, 8)>>>(U2, u2h, u2l, HH);
    permute_bias_kernel<<<FH / 256, 256>>>(b1, b1p);
    permute_bias_kernel<<<FH / 256, 256>>>(b2, b2p);

    const dim3 ggrid(FH / 128, MROWS / 128);   // (32, 128)

    // layer 1: xz = x @ W1p + b1p  (rows remapped to [t][b])
    hgemm_kernel<1><<<ggrid, 256, GEMM_SMEM>>>(x16, w1h, w1l, b1p, xz, DD);
    zero_state_kernel<<<(BB * HH + 255) / 256, 256>>>();
    lstm_persist<1><<<128, 256, PERS_SMEM>>>(
        xz, u1h, u1l,
        hs, hs + BB * HH,
        h1s, (float*)0, barc, bars);

    // layer 2: xz = h1seq @ W2p + b2p  (rows already [t][b])
    hgemm_kernel<0><<<ggrid, 256, GEMM_SMEM>>>(h1s, w2h, w2l, b2p, xz, HH);
    zero_state_kernel<<<(BB * HH + 255) / 256, 256>>>();
    lstm_persist<2><<<128, 256, PERS_SMEM>>>(
        xz, u2h, u2l,
        hs, hs + BB * HH,
        (f16*)0, hfp, barc, bars);

    // final dense: out = h_last @ Wd + bd
    gemm64_kernel<<<dim3(OO / 64, BB / 64), 256>>>(hfp, Wd, bd, out, HH, OO);
}

// round 17
// speedup vs baseline: 5.8369x; 1.0871x over previous
#include <cuda_runtime.h>
#include <cuda_fp16.h>
#include <math.h>
#include <stdint.h>

typedef __half f16;

#define BB 64
#define TT 256
#define DD 512
#define HH 1024
#define FH 4096
#define OO 512
#define MROWS (BB*TT)

// ---------------- scratch (device globals; no allocation) ----------------
__device__ float g_xz[(size_t)MROWS * FH];
__device__ f16   g_x16[(size_t)MROWS * DD];
__device__ f16   g_w1t_hi[(size_t)FH * DD];
__device__ f16   g_w1t_lo[(size_t)FH * DD];
__device__ f16   g_u1t_hi[(size_t)FH * HH];
__device__ f16   g_u1t_lo[(size_t)FH * HH];
__device__ f16   g_w2t_hi[(size_t)FH * HH];
__device__ f16   g_w2t_lo[(size_t)FH * HH];
__device__ f16   g_u2t_hi[(size_t)FH * HH];
__device__ f16   g_u2t_lo[(size_t)FH * HH];
__device__ f16   g_h1seq[(size_t)MROWS * HH];
__device__ f16   g_hs[2][BB * HH];
__device__ float g_hfp[BB * HH];
__device__ float g_b1p[FH];
__device__ float g_b2p[FH];
__device__ int   g_barcnt;
__device__ int   g_barsense;

// ---------------- ptx helpers (arch-generic) ----------------
__device__ __forceinline__ uint32_t smem_u32(const void* p) {
    return (uint32_t)__cvta_generic_to_shared(p);
}
__device__ __forceinline__ void ldsm_x4(uint32_t& r0, uint32_t& r1, uint32_t& r2,
                                        uint32_t& r3, uint32_t a) {
    asm volatile("ldmatrix.sync.aligned.m8n8.x4.shared.b16 {%0,%1,%2,%3}, [%4];"
                 : "=r"(r0), "=r"(r1), "=r"(r2), "=r"(r3) : "r"(a));
}
__device__ __forceinline__ void mma16816(float* d, uint32_t a0, uint32_t a1,
                                         uint32_t a2, uint32_t a3,
                                         uint32_t b0, uint32_t b1) {
    asm volatile(
        "mma.sync.aligned.m16n8k16.row.col.f32.f16.f16.f32 "
        "{%0,%1,%2,%3}, {%4,%5,%6,%7}, {%8,%9}, {%0,%1,%2,%3};"
        : "+f"(d[0]), "+f"(d[1]), "+f"(d[2]), "+f"(d[3])
        : "r"(a0), "r"(a1), "r"(a2), "r"(a3), "r"(b0), "r"(b1));
}
__device__ __forceinline__ void cpasync16(uint32_t s, const void* g) {
    asm volatile("cp.async.cg.shared.global [%0], [%1], 16;" :: "r"(s), "l"(g));
}
#define CP_COMMIT() asm volatile("cp.async.commit_group;" ::: "memory")
#define CP_WAIT1()  asm volatile("cp.async.wait_group 1;" ::: "memory")
#define CP_WAIT0()  asm volatile("cp.async.wait_group 0;" ::: "memory")

__device__ __forceinline__ float tanha(float x) {
    float y;
    asm("tanh.approx.f32 %0, %1;" : "=f"(y) : "f"(x));
    return y;
}

__device__ __forceinline__ uint32_t swz(int row, int col16) {
    return (uint32_t)(row * 128 + ((col16 ^ (row & 7)) * 16));
}

// cp.async a [R rows x 64 f16] chunk (kc-th) from K-major gmem into swizzled smem
template <int R, int NT>
__device__ __forceinline__ void cp_tile(const f16* __restrict__ src, size_t row0,
                                        int K, int kc, uint32_t sdst, int tid) {
#pragma unroll
    for (int i = tid; i < R * 8; i += NT) {
        int r = i >> 3, j = i & 7;
        cpasync16(sdst + swz(r, j), src + (row0 + r) * (size_t)K + (size_t)kc * 64 + j * 8);
    }
}

// ---------------- preprocessing ----------------
__global__ void conv_x_kernel(const float* __restrict__ x, f16* __restrict__ o, int n) {
    int i = blockIdx.x * blockDim.x + threadIdx.x;
    if (i < n) o[i] = __float2half(x[i]);
}

// W [K][4096] -> out [4096][K] K-major, gate permute n' = 4u+g (src n = g*1024+u), fp16 hi/lo
__global__ void split_wT_kernel(const float* __restrict__ W, f16* __restrict__ hiT,
                                f16* __restrict__ loT, int K) {
    __shared__ float t[32][33];
    int kb = blockIdx.y * 32, nb = blockIdx.x * 32;
    for (int r = threadIdx.y; r < 32; r += 8)
        t[r][threadIdx.x] = W[(size_t)(kb + r) * FH + nb + threadIdx.x];
    __syncthreads();
    for (int c = threadIdx.y; c < 32; c += 8) {
        int n = nb + c;
        int np = ((n & 1023) << 2) | (n >> 10);
        float v = t[threadIdx.x][c];
        f16 h = __float2half(v);
        hiT[(size_t)np * K + kb + threadIdx.x] = h;
        loT[(size_t)np * K + kb + threadIdx.x] = __float2half(v - __half2float(h));
    }
}

__global__ void permute_bias_kernel(const float* __restrict__ b, float* __restrict__ bp) {
    int np = blockIdx.x * blockDim.x + threadIdx.x;
    if (np < FH) { int u = np >> 2, g = np & 3; bp[np] = b[g * HH + u]; }
}

__global__ void zero_state_kernel() {
    int i = blockIdx.x * blockDim.x + threadIdx.x;
    if (i < (BB * HH) / 2) ((uint32_t*)g_hs[0])[i] = 0u;   // zero h as u32 pairs
    if (i == 0) { g_barcnt = 0; g_barsense = 0; }
}

// ---------------- big fp16 2-MMA GEMM: out[M][4096] = A @ (Bhi+Blo)^T + bias ----------------
// Tile 128x128, BK=64, 256 thr (8 warps: 2M x 4N), warp tile 64x32.
// REMAP=1: orow = (m&255)*64 + (m>>8)
template <int REMAP>
__global__ __launch_bounds__(256) void hgemm_kernel(
    const f16* __restrict__ A,
    const f16* __restrict__ Bhi, const f16* __restrict__ Blo,
    const float* __restrict__ bias, float* __restrict__ out, int K)
{
    extern __shared__ char smem[];
    const int tid = threadIdx.x;
    const int wid = tid >> 5, lane = tid & 31;
    const int wm = wid >> 2, wn = wid & 3;
    const int m0 = blockIdx.y * 128, n0 = blockIdx.x * 128;
    uint32_t sb = smem_u32(smem);
    const int nkc = K >> 6;

    // stage s at s*49152: A@0 (16K), Bhi@16384 (16K), Blo@32768 (16K)
    {
        uint32_t st = sb;
        cp_tile<128, 256>(A,   m0, K, 0, st, tid);
        cp_tile<128, 256>(Bhi, n0, K, 0, st + 16384, tid);
        cp_tile<128, 256>(Blo, n0, K, 0, st + 32768, tid);
        CP_COMMIT();
    }

    float acc[4][4][4] = {};   // [mt][nb][reg]

    const int a_row = wm * 64 + (lane & 7) + ((lane >> 3) & 1) * 8;  // + mt*16
    const int a_cp  = (lane >> 4) & 1;
    const int b_row = wn * 32 + (lane & 7) + ((lane >> 4) & 1) * 8;  // + nbp*16
    const int b_cp  = (lane >> 3) & 1;

    for (int kc = 0; kc < nkc; ++kc) {
        int cur = kc & 1;
        if (kc + 1 < nkc) {
            uint32_t st = sb + (uint32_t)(cur ^ 1) * 49152u;
            cp_tile<128, 256>(A,   m0, K, kc + 1, st, tid);
            cp_tile<128, 256>(Bhi, n0, K, kc + 1, st + 16384, tid);
            cp_tile<128, 256>(Blo, n0, K, kc + 1, st + 32768, tid);
            CP_COMMIT();
            CP_WAIT1();
        } else {
            CP_WAIT0();
        }
        __syncthreads();
        uint32_t stA = sb + (uint32_t)cur * 49152u;
#pragma unroll
        for (int kj = 0; kj < 4; ++kj) {
            uint32_t bh[4][2], bl[4][2];
#pragma unroll
            for (int nbp = 0; nbp < 2; ++nbp) {
                uint32_t baddr = stA + 16384 + swz(b_row + nbp * 16, kj * 2 + b_cp);
                ldsm_x4(bh[nbp * 2][0], bh[nbp * 2][1], bh[nbp * 2 + 1][0], bh[nbp * 2 + 1][1], baddr);
                ldsm_x4(bl[nbp * 2][0], bl[nbp * 2][1], bl[nbp * 2 + 1][0], bl[nbp * 2 + 1][1], baddr + 16384);
            }
#pragma unroll
            for (int mt = 0; mt < 4; ++mt) {
                uint32_t a0, a1, a2, a3;
                ldsm_x4(a0, a1, a2, a3, stA + swz(a_row + mt * 16, kj * 2 + a_cp));
#pragma unroll
                for (int nb = 0; nb < 4; ++nb) {
                    mma16816(acc[mt][nb], a0, a1, a2, a3, bh[nb][0], bh[nb][1]);
                    mma16816(acc[mt][nb], a0, a1, a2, a3, bl[nb][0], bl[nb][1]);
                }
            }
        }
        __syncthreads();
    }

#pragma unroll
    for (int mt = 0; mt < 4; ++mt) {
#pragma unroll
        for (int half_ = 0; half_ < 2; ++half_) {
            int m = m0 + wm * 64 + mt * 16 + (lane >> 2) + half_ * 8;
            size_t orow = REMAP ? ((size_t)(m & 255) * 64 + (size_t)(m >> 8)) : (size_t)m;
#pragma unroll
            for (int nb = 0; nb < 4; ++nb) {
                int n = n0 + wn * 32 + nb * 8 + 2 * (lane & 3);
                float2 v;
                v.x = acc[mt][nb][half_ * 2 + 0] + bias[n];
                v.y = acc[mt][nb][half_ * 2 + 1] + bias[n + 1];
                *(float2*)(out + orow * FH + n) = v;
            }
        }
    }
}

// ---------------- persistent LSTM layer (single-fp16 U: 1 MMA per tile) ----------------
// 128 CTAs x 256 thr (8 warps, 4M x 2N warp tiles of 16x16). CTA owns 32 permuted cols = 8 units.
// U single fp16 (64 KB) resident in SMEM; h single fp16 streamed; c-state in SMEM.
// SMEM: U@0(64K) hstages@65536(2x8K) zs@81920(9216B) cs@91136(2048B)  -> 93184 total
template <int LAYER>
__global__ __launch_bounds__(256) void lstm_persist(
    const float* __restrict__ xz,
    const f16* __restrict__ Uhi,
    f16* __restrict__ h0, f16* __restrict__ h1,
    f16* __restrict__ seq, float* __restrict__ hfp,
    int* __restrict__ barcnt, volatile int* __restrict__ barsense)
{
    extern __shared__ char smem[];
    const int tid = threadIdx.x;
    const int wid = tid >> 5, lane = tid & 31;
    const int wm = wid & 3, wn = wid >> 2;
    const int n0 = blockIdx.x * 32;
    const int u0 = blockIdx.x * 8;
    uint32_t sb = smem_u32(smem);
    float* zs = (float*)(smem + 81920);
    float* cs = (float*)(smem + 91136);

    // load U tile once: 16 kblocks x (32 rows x 64 k fp16 = 4KB)
    for (int i = tid; i < 4096; i += 256) {
        int kb = i >> 8, r = (i >> 3) & 31, j = i & 7;
        size_t goff = (size_t)(n0 + r) * HH + kb * 64 + j * 8;
        uint32_t off = (uint32_t)(kb * 4096) + swz(r, j);
        *(uint4*)(smem + off) = *(const uint4*)(Uhi + goff);
    }
    for (int i = tid; i < 512; i += 256) cs[i] = 0.0f;

    int sense = 0;
    const int a_row = wm * 16 + (lane & 7) + ((lane >> 3) & 1) * 8;
    const int a_cp  = (lane >> 4) & 1;
    const int b_row = wn * 16 + (lane & 7) + ((lane >> 4) & 1) * 8;
    const int b_cp  = (lane >> 3) & 1;
    __syncthreads();

    for (int t = 0; t < TT; ++t) {
        const f16* hin = (t & 1) ? h1 : h0;
        f16* hout = (t & 1) ? h0 : h1;
        const float* xzt = xz + (size_t)t * BB * FH;

        float acc[2][4] = {};   // [nb][reg]

        {   // prime stage 0 with h chunk 0 (64 rows x 64 k fp16 = 8KB)
            uint32_t s0 = sb + 65536;
#pragma unroll
            for (int i = tid; i < 512; i += 256) {
                int r = i >> 3, j = i & 7;
                cpasync16(s0 + swz(r, j), hin + (size_t)r * HH + j * 8);
            }
            CP_COMMIT();
        }
        for (int kc = 0; kc < 16; ++kc) {
            int cur = kc & 1;
            if (kc + 1 < 16) {
                uint32_t sn = sb + 65536 + (uint32_t)(cur ^ 1) * 8192u;
#pragma unroll
                for (int i = tid; i < 512; i += 256) {
                    int r = i >> 3, j = i & 7;
                    cpasync16(sn + swz(r, j), hin + (size_t)r * HH + (kc + 1) * 64 + j * 8);
                }
                CP_COMMIT();
                CP_WAIT1();
            } else {
                CP_WAIT0();
            }
            __syncthreads();
            uint32_t hA = sb + 65536 + (uint32_t)cur * 8192u;
            uint32_t uB = sb + (uint32_t)kc * 4096u;
#pragma unroll
            for (int kj = 0; kj < 4; ++kj) {
                uint32_t a0, a1, a2, a3;
                ldsm_x4(a0, a1, a2, a3, hA + swz(a_row, kj * 2 + a_cp));
                uint32_t bh[2][2];
                uint32_t baddr = uB + swz(b_row, kj * 2 + b_cp);
                ldsm_x4(bh[0][0], bh[0][1], bh[1][0], bh[1][1], baddr);
                mma16816(acc[0], a0, a1, a2, a3, bh[0][0], bh[0][1]);
                mma16816(acc[1], a0, a1, a2, a3, bh[1][0], bh[1][1]);
            }
            __syncthreads();
        }
        // write z tile to smem (stride 36 floats)
        {
            int m = wm * 16 + (lane >> 2);
            int nbase = wn * 16 + 2 * (lane & 3);
#pragma unroll
            for (int nb = 0; nb < 2; ++nb) {
                int nn = nbase + nb * 8;
                zs[m * 36 + nn]           = acc[nb][0];
                zs[m * 36 + nn + 1]       = acc[nb][1];
                zs[(m + 8) * 36 + nn]     = acc[nb][2];
                zs[(m + 8) * 36 + nn + 1] = acc[nb][3];
            }
        }
        __syncthreads();
        // epilogue: thread -> (b = tid/4, 2 units); tanh.approx activations
        {
            int b = tid >> 2;
            int uu0 = (tid & 3) * 2;
            const float* xzb = xzt + (size_t)b * FH + n0;
            const float* zrow = zs + b * 36;
#pragma unroll
            for (int q = 0; q < 2; ++q) {
                int uu = uu0 + q;
                float4 xv = *(const float4*)(xzb + uu * 4);
                float zi = zrow[uu * 4 + 0] + xv.x;
                float zf = zrow[uu * 4 + 1] + xv.y;
                float zg = zrow[uu * 4 + 2] + xv.z;
                float zo = zrow[uu * 4 + 3] + xv.w;
                float si = 0.5f * tanha(0.5f * zi) + 0.5f;
                float sf = 0.5f * tanha(0.5f * zf) + 0.5f;
                float so = 0.5f * tanha(0.5f * zo) + 0.5f;
                float tg = tanha(zg);
                int ci = b * 8 + uu;
                float cn = sf * cs[ci] + si * tg;
                cs[ci] = cn;
                float hn = so * tanha(cn);
                hout[(size_t)b * HH + u0 + uu] = __float2half(hn);
                if (LAYER == 1) {
                    seq[(size_t)t * (BB * HH) + b * HH + u0 + uu] = __float2half(hn);
                } else if (t == TT - 1) {
                    hfp[b * HH + u0 + uu] = hn;
                }
            }
        }
        // grid barrier (sense-reversal; 128 resident CTAs)
        __syncthreads();
        if (tid == 0) {
            int s = sense ^ 1;
            __threadfence();
            if (atomicAdd(barcnt, 1) == 127) {
                *barcnt = 0;
                __threadfence();
                *barsense = s;
            } else {
                while (*barsense != s) { __nanosleep(40); }
            }
            __threadfence();
        }
        sense ^= 1;
        __syncthreads();
    }
}

// ---------------- fp32 GEMM for the tiny final dense ----------------
__global__ __launch_bounds__(256) void gemm64_kernel(
    const float* __restrict__ A, const float* __restrict__ Wt,
    const float* __restrict__ bias, float* __restrict__ Cout,
    int K, int N)
{
    __shared__ float As[2][16 * 68];
    __shared__ float Bs[2][16 * 64];
    const int m0 = blockIdx.y * 64;
    const int n0 = blockIdx.x * 64;
    const int tid = threadIdx.x;
    const int tn = tid & 15;
    const int tm = tid >> 4;
    const int am = tid >> 2;
    const int ak = (tid & 3) * 4;
    const int bk = tid >> 4;
    const int bn = (tid & 15) * 4;
    const float* Aptr = A + (size_t)(m0 + am) * K + ak;
    const float* Bptr = Wt + (size_t)bk * N + n0 + bn;
    float acc[4][4] = {};
    float4 areg, breg;
    const int nchunk = K / 16;
    areg = *(const float4*)(Aptr);
    breg = *(const float4*)(Bptr);
    {
        float* as = As[0]; float* bs = Bs[0];
        as[(ak + 0) * 68 + am] = areg.x; as[(ak + 1) * 68 + am] = areg.y;
        as[(ak + 2) * 68 + am] = areg.z; as[(ak + 3) * 68 + am] = areg.w;
        *(float4*)&bs[bk * 64 + bn] = breg;
    }
    __syncthreads();
    for (int c = 0; c < nchunk; ++c) {
        if (c + 1 < nchunk) {
            areg = *(const float4*)(Aptr + (c + 1) * 16);
            breg = *(const float4*)(Bptr + (size_t)(c + 1) * 16 * N);
        }
        const float* as = As[c & 1];
        const float* bs = Bs[c & 1];
#pragma unroll
        for (int k = 0; k < 16; ++k) {
            float4 a4 = *(const float4*)&as[k * 68 + 4 * tm];
            float4 b4 = *(const float4*)&bs[k * 64 + 4 * tn];
            acc[0][0] += a4.x * b4.x; acc[0][1] += a4.x * b4.y;
            acc[0][2] += a4.x * b4.z; acc[0][3] += a4.x * b4.w;
            acc[1][0] += a4.y * b4.x; acc[1][1] += a4.y * b4.y;
            acc[1][2] += a4.y * b4.z; acc[1][3] += a4.y * b4.w;
            acc[2][0] += a4.z * b4.x; acc[2][1] += a4.z * b4.y;
            acc[2][2] += a4.z * b4.z; acc[2][3] += a4.z * b4.w;
            acc[3][0] += a4.w * b4.x; acc[3][1] += a4.w * b4.y;
            acc[3][2] += a4.w * b4.z; acc[3][3] += a4.w * b4.w;
        }
        if (c + 1 < nchunk) {
            float* asw = As[(c + 1) & 1]; float* bsw = Bs[(c + 1) & 1];
            asw[(ak + 0) * 68 + am] = areg.x; asw[(ak + 1) * 68 + am] = areg.y;
            asw[(ak + 2) * 68 + am] = areg.z; asw[(ak + 3) * 68 + am] = areg.w;
            *(float4*)&bsw[bk * 64 + bn] = breg;
        }
        __syncthreads();
    }
#pragma unroll
    for (int i = 0; i < 4; ++i) {
        int m = m0 + 4 * tm + i;
        float4 v;
        v.x = acc[i][0] + bias[n0 + 4 * tn + 0];
        v.y = acc[i][1] + bias[n0 + 4 * tn + 1];
        v.z = acc[i][2] + bias[n0 + 4 * tn + 2];
        v.w = acc[i][3] + bias[n0 + 4 * tn + 3];
        *(float4*)&Cout[(size_t)m * N + n0 + 4 * tn] = v;
    }
}

// ---------------- launch ----------------
extern "C" void kernel_launch(void* const* d_in, const int* in_sizes, int n_in,
                              void* d_out, int out_size)
{
    const float* x  = (const float*)d_in[0];
    const float* W1 = (const float*)d_in[1];
    const float* U1 = (const float*)d_in[2];
    const float* b1 = (const float*)d_in[3];
    const float* W2 = (const float*)d_in[4];
    const float* U2 = (const float*)d_in[5];
    const float* b2 = (const float*)d_in[6];
    const float* Wd = (const float*)d_in[7];
    const float* bd = (const float*)d_in[8];
    float* out = (float*)d_out;

#define SYM(v, s) do { void* p_; cudaGetSymbolAddress(&p_, s); v = (decltype(v))p_; } while (0)
    float *xz, *b1p, *b2p, *hfp;
    f16 *x16, *w1h, *w1l, *u1h, *u1l, *w2h, *w2l, *u2h, *u2l, *h1s, *hs;
    int* barc; int* bars;
    SYM(xz, g_xz); SYM(b1p, g_b1p); SYM(b2p, g_b2p); SYM(hfp, g_hfp);
    SYM(x16, g_x16);
    SYM(w1h, g_w1t_hi); SYM(w1l, g_w1t_lo); SYM(u1h, g_u1t_hi); SYM(u1l, g_u1t_lo);
    SYM(w2h, g_w2t_hi); SYM(w2l, g_w2t_lo); SYM(u2h, g_u2t_hi); SYM(u2l, g_u2t_lo);
    SYM(h1s, g_h1seq); SYM(hs, g_hs);
    SYM(barc, g_barcnt); SYM(bars, g_barsense);
#undef SYM

    const int GEMM_SMEM = 2 * 49152;    // 98304
    const int PERS_SMEM = 93184;
    cudaFuncSetAttribute(hgemm_kernel<0>, cudaFuncAttributeMaxDynamicSharedMemorySize, GEMM_SMEM);
    cudaFuncSetAttribute(hgemm_kernel<1>, cudaFuncAttributeMaxDynamicSharedMemorySize, GEMM_SMEM);
    cudaFuncSetAttribute(lstm_persist<1>, cudaFuncAttributeMaxDynamicSharedMemorySize, PERS_SMEM);
    cudaFuncSetAttribute(lstm_persist<2>, cudaFuncAttributeMaxDynamicSharedMemorySize, PERS_SMEM);

    // preprocessing
    conv_x_kernel<<<(MROWS * DD + 255) / 256, 256>>>(x, x16, MROWS * DD);
    split_wT_kernel<<<dim3(FH / 32, DD / 32), dim3(32, 8)>>>(W1, w1h, w1l, DD);
    split_wT_kernel<<<dim3(FH / 32, HH / 32), dim3(32, 8)>>>(U1, u1h, u1l, HH);
    split_wT_kernel<<<dim3(FH / 32, HH / 32), dim3(32, 8)>>>(W2, w2h, w2l, HH);
    split_wT_kernel<<<dim3(FH / 32, HH / 32), dim3(32, 8)>>>(U2, u2h, u2l, HH);
    permute_bias_kernel<<<FH / 256, 256>>>(b1, b1p);
    permute_bias_kernel<<<FH / 256, 256>>>(b2, b2p);

    const dim3 ggrid(FH / 128, MROWS / 128);   // (32, 128)

    // layer 1: xz = x @ W1p + b1p  (rows remapped to [t][b])
    hgemm_kernel<1><<<ggrid, 256, GEMM_SMEM>>>(x16, w1h, w1l, b1p, xz, DD);
    zero_state_kernel<<<(BB * HH + 255) / 256, 256>>>();
    lstm_persist<1><<<128, 256, PERS_SMEM>>>(
        xz, u1h,
        hs, hs + BB * HH,
        h1s, (float*)0, barc, bars);

    // layer 2: xz = h1seq @ W2p + b2p  (rows already [t][b])
    hgemm_kernel<0><<<ggrid, 256, GEMM_SMEM>>>(h1s, w2h, w2l, b2p, xz, HH);
    zero_state_kernel<<<(BB * HH + 255) / 256, 256>>>();
    lstm_persist<2><<<128, 256, PERS_SMEM>>>(
        xz, u2h,
        hs, hs + BB * HH,
        (f16*)0, hfp, barc, bars);

    // final dense: out = h_last @ Wd + bd
    gemm64_kernel<<<dim3(OO / 64, BB / 64), 256>>>(hfp, Wd, bd, out, HH, OO);
}